// round 11
// baseline (speedup 1.0000x reference)
#include <cuda_runtime.h>
#include <cuda_bf16.h>
#include <cstdint>

#define B_      1024
#define L_      50
#define K_      20
#define D_      64
#define NITEMS  100000
#define NUSERS  10000
#define ALPHA   0.2f

#define NT_PAD   12512              // n8-tiles padded to multiple of 16
#define NGROUPS  (NT_PAD / 16)      // 782 groups of 128 cols
#define STRIPS   8
#define SLOTS    18                 // 144 CTAs, one wave

__device__ float g_pu[B_ * D_];

__device__ __forceinline__ uint32_t f2tf32(float x) {
    uint32_t u;
    asm("cvt.rn.tf32.f32 %0, %1;" : "=r"(u) : "f"(x));
    return u;
}
__device__ __forceinline__ uint32_t smem_u32(const void* p) {
    uint32_t a;
    asm("{ .reg .u64 t; cvta.to.shared.u64 t, %1; cvt.u32.u64 %0, t; }"
        : "=r"(a) : "l"(p));
    return a;
}
// 16B async copy with runtime src-size (0 -> zero-fill)
__device__ __forceinline__ void cp_async16z(uint32_t dst, const void* src,
                                            unsigned sbytes) {
    asm volatile("cp.async.cg.shared.global [%0], [%1], 16, %2;"
                 :: "r"(dst), "l"(src), "r"(sbytes) : "memory");
}
#define CP_COMMIT() asm volatile("cp.async.commit_group;" ::: "memory")
#define CP_WAIT(n)  asm volatile("cp.async.wait_group %0;" :: "n"(n) : "memory")

__device__ __forceinline__ void mma_tf32(float& c0, float& c1, float& c2, float& c3,
                                         uint32_t a0, uint32_t a1, uint32_t a2, uint32_t a3,
                                         uint32_t b0, uint32_t b1) {
    asm volatile("mma.sync.aligned.m16n8k8.row.col.f32.tf32.tf32.f32 "
                 "{%0,%1,%2,%3}, {%4,%5,%6,%7}, {%8,%9}, {%0,%1,%2,%3};"
                 : "+f"(c0), "+f"(c1), "+f"(c2), "+f"(c3)
                 : "r"(a0), "r"(a1), "r"(a2), "r"(a3), "r"(b0), "r"(b1));
}

__device__ __forceinline__ float tree_sum20(const float* s) {
    float t1[10];
#pragma unroll
    for (int i = 0; i < 10; i++) t1[i] = s[2 * i] + s[2 * i + 1];
    float t2[5];
#pragma unroll
    for (int i = 0; i < 5; i++) t2[i] = t1[2 * i] + t1[2 * i + 1];
    return ((t2[0] + t2[1]) + (t2[2] + t2[3])) + t2[4];
}

// ===========================================================================
// Prep kernel: recurrence ONLY (B transform eliminated).
// 128 blocks x 256 threads, 8 warps = 8 batch rows per block.
// ===========================================================================
#define RECUR_BLOCKS 128

__global__ void __launch_bounds__(256)
recur_kernel(const float* __restrict__ item,
             const float* __restrict__ user,
             const float* __restrict__ mem_init,
             const int*   __restrict__ user_id,
             const int*   __restrict__ seq,
             const int*   __restrict__ seq_len)
{
    __shared__ int sseq[8 * L_];
    const int tid  = threadIdx.x;
    const int wid  = tid >> 5;
    const int lane = tid & 31;
    const int b    = blockIdx.x * 8 + wid;

    for (int i = tid; i < 8 * L_; i += 256)
        sseq[i] = seq[blockIdx.x * 8 * L_ + i];
    __syncthreads();

    float m0[K_], m1[K_];
    const float* mi = mem_init + (size_t)b * K_ * D_;
#pragma unroll
    for (int k = 0; k < K_; k++) {
        m0[k] = mi[k * D_ + lane];
        m1[k] = mi[k * D_ + lane + 32];
    }

    const int T = seq_len[b];
    const int* sq = sseq + wid * L_;

    for (int t0 = 0; t0 < T; t0 += 8) {
        int nt = min(8, T - t0);
        float e0[8], e1[8];
#pragma unroll
        for (int i = 0; i < 8; i++) {
            if (i < nt) {
                int idx = sq[t0 + i];
                e0[i] = __ldg(item + (size_t)idx * D_ + lane);
                e1[i] = __ldg(item + (size_t)idx * D_ + lane + 32);
            }
        }
#pragma unroll
        for (int i = 0; i < 8; i++) {
            if (i >= nt) break;
            float s[K_];
#pragma unroll
            for (int k = 0; k < K_; k++) {
                float p = fmaf(m0[k], e0[i], m1[k] * e1[i]);
#pragma unroll
                for (int off = 16; off > 0; off >>= 1)
                    p += __shfl_xor_sync(0xffffffffu, p, off);
                s[k] = p;
            }
#pragma unroll
            for (int k = 0; k < K_; k++) s[k] = __expf(s[k]);
            float inv = __fdividef(1.f, tree_sum20(s));
            float er0 = __fdividef(1.f, 1.f + __expf(-e0[i]));
            float er1 = __fdividef(1.f, 1.f + __expf(-e1[i]));
            float ex0 = __expf(2.f * e0[i]);
            float ex1 = __expf(2.f * e1[i]);
            float ad0 = __fdividef(ex0 - 1.f, ex0 + 1.f);
            float ad1 = __fdividef(ex1 - 1.f, ex1 + 1.f);
#pragma unroll
            for (int k = 0; k < K_; k++) {
                float z = s[k] * inv;
                m0[k] = m0[k] * (1.f - z * er0) + z * ad0;
                m1[k] = m1[k] * (1.f - z * er1) + z * ad1;
            }
        }
    }

    int lidx = sq[L_ - 1];
    float l0 = __ldg(item + (size_t)lidx * D_ + lane);
    float l1 = __ldg(item + (size_t)lidx * D_ + lane + 32);

    float s[K_];
#pragma unroll
    for (int k = 0; k < K_; k++) {
        float p = fmaf(m0[k], l0, m1[k] * l1);
#pragma unroll
        for (int off = 16; off > 0; off >>= 1)
            p += __shfl_xor_sync(0xffffffffu, p, off);
        s[k] = __expf(p);
    }
    float inv = __fdividef(1.f, tree_sum20(s));

    float p0 = 0.f, p1 = 0.f;
#pragma unroll
    for (int k = 0; k < K_; k++) {
        float z = s[k] * inv;
        p0 = fmaf(z, m0[k], p0);
        p1 = fmaf(z, m1[k], p1);
    }

    int uid = user_id[b];
    g_pu[b * D_ + lane]      = user[(size_t)uid * D_ + lane]      + ALPHA * p0;
    g_pu[b * D_ + lane + 32] = user[(size_t)uid * D_ + lane + 32] + ALPHA * p1;
}

// ===========================================================================
// Persistent GEMM reading RAW item rows (no pre-transform).
// 144 CTAs (8 strips x 18 slots), 512 thr = 16 warps (4M x 4N), warp 32x32.
// A in registers (tf32 RN).  B: 3-stage cp.async ring of raw rows, PADDED to
// 68 floats/row -> per-MMA LDS.32 b-loads are bank-conflict-free:
//   bank(b0) = (4n + 8ks + t) mod 32, n === g (mod 8) -> 4g + t distinct.
// B converted to tf32 (RN) in registers right before the MMA.
// Epilogue: natural-order STG.64 streaming stores.
// ===========================================================================
#define ROW_F   68                            // padded floats per row
#define ROW_B   272
#define TILE_B  (128 * ROW_B)                 // 34816 bytes per group
#define GEMM_SMEM_BYTES (1024 + 3 * TILE_B)   // 105472

__global__ void __launch_bounds__(512, 1)
gemm_persist(const float* __restrict__ item, float* __restrict__ C)
{
    extern __shared__ char smem[];
    const uint32_t bufs = smem_u32(smem) + 1024;
    float* const sBf = (float*)(smem + 1024);

    const int tid  = threadIdx.x;
    const int wid  = tid >> 5;
    const int lane = tid & 31;
    const int wm   = wid >> 2;               // 0..3 (32 rows)
    const int wn   = wid & 3;                // 0..3 (32 cols)
    const int g    = lane >> 2;
    const int t    = lane & 3;

    const int strip = blockIdx.x & 7;
    const int slot  = blockIdx.x >> 3;

    // copy assignment: thread owns ONE local row, granules f40+{0,4,8,12}
    const int crow = tid & 127;              // local row
    const int f40  = tid >> 7;               // first granule (0..3)

    // ---- A: this warp's 32-row slice of pu -> registers (tf32 RN) ----
    uint4 a[2][8];
    {
        const float* pu = g_pu + (size_t)(strip * 128 + wm * 32) * 64;
#pragma unroll
        for (int mi = 0; mi < 2; mi++) {
            int r0 = mi * 16 + g;
#pragma unroll
            for (int ks = 0; ks < 8; ks++) {
                int k0 = ks * 8 + t;
                a[mi][ks].x = f2tf32(pu[r0 * 64 + k0]);
                a[mi][ks].y = f2tf32(pu[(r0 + 8) * 64 + k0]);
                a[mi][ks].z = f2tf32(pu[r0 * 64 + k0 + 4]);
                a[mi][ks].w = f2tf32(pu[(r0 + 8) * 64 + k0 + 4]);
            }
        }
    }

    const int row_base = strip * 128 + wm * 32;

    // ---- prologue: stage raw groups for iter 0,1 ----
#pragma unroll
    for (int pf = 0; pf < 2; pf++) {
        int grp = slot + pf * SLOTS;         // < NGROUPS always (max 35)
        int grow = grp * 128 + crow;
        unsigned sb = (grow < NITEMS) ? 16u : 0u;
        const float* src = item + (size_t)grow * 64;
        uint32_t dst = bufs + pf * TILE_B + crow * ROW_B;
#pragma unroll
        for (int i = 0; i < 4; i++) {
            int f4 = f40 + 4 * i;
            cp_async16z(dst + f4 * 16, src + f4 * 4, sb);
        }
        CP_COMMIT();
    }

    int iter = 0;
    for (int grp = slot; grp < NGROUPS; grp += SLOTS, iter++) {
        const int buf = iter - (iter / 3) * 3;
        CP_WAIT(1);
        __syncthreads();

        // prefetch iter+2 into the just-freed buffer
        {
            int nxt = grp + 2 * SLOTS;
            if (nxt < NGROUPS) {
                const int pbuf = (buf + 2 >= 3) ? buf - 1 : buf + 2;
                int grow = nxt * 128 + crow;
                unsigned sb = (grow < NITEMS) ? 16u : 0u;
                const float* src = item + (size_t)grow * 64;
                uint32_t dst = bufs + pbuf * TILE_B + crow * ROW_B;
#pragma unroll
                for (int i = 0; i < 4; i++) {
                    int f4 = f40 + 4 * i;
                    cp_async16z(dst + f4 * 16, src + f4 * 4, sb);
                }
            }
            CP_COMMIT();
        }

        float acc[2][4][4];
#pragma unroll
        for (int i = 0; i < 2; i++)
#pragma unroll
            for (int j = 0; j < 4; j++)
#pragma unroll
                for (int q = 0; q < 4; q++) acc[i][j][q] = 0.f;

        const float* Bs = sBf + buf * (TILE_B / 4);
#pragma unroll
        for (int ks = 0; ks < 8; ks++) {
#pragma unroll
            for (int sub = 0; sub < 4; sub++) {
                const int n = wn * 32 + sub * 8 + g;
                const float* bp = Bs + n * ROW_F + ks * 8 + t;
                uint32_t b0 = f2tf32(bp[0]);
                uint32_t b1 = f2tf32(bp[4]);
#pragma unroll
                for (int mi = 0; mi < 2; mi++)
                    mma_tf32(acc[mi][sub][0], acc[mi][sub][1],
                             acc[mi][sub][2], acc[mi][sub][3],
                             a[mi][ks].x, a[mi][ks].y, a[mi][ks].z, a[mi][ks].w,
                             b0, b1);
            }
        }

        // ---- epilogue: natural-order STG.64 streaming stores ----
#pragma unroll
        for (int mi = 0; mi < 2; mi++) {
            int row0 = row_base + mi * 16 + g;
#pragma unroll
            for (int sub = 0; sub < 4; sub++) {
                int base8 = grp * 128 + wn * 32 + sub * 8;
                if (base8 < NITEMS) {        // NITEMS % 8 == 0
                    int col = base8 + 2 * t;
                    __stcs((float2*)(C + (size_t)row0 * NITEMS + col),
                           make_float2(acc[mi][sub][0], acc[mi][sub][1]));
                    __stcs((float2*)(C + (size_t)(row0 + 8) * NITEMS + col),
                           make_float2(acc[mi][sub][2], acc[mi][sub][3]));
                }
            }
        }
    }
}

// ===========================================================================
extern "C" void kernel_launch(void* const* d_in, const int* in_sizes, int n_in,
                              void* d_out, int out_size)
{
    const float* item_table  = (const float*)d_in[0];
    const float* user_table  = (const float*)d_in[1];
    const float* memory_init = (const float*)d_in[2];
    const int*   user_id     = (const int*)d_in[3];
    const int*   seq         = (const int*)d_in[4];
    const int*   seq_length  = (const int*)d_in[5];
    float*       scores      = (float*)d_out;

    cudaFuncSetAttribute(gemm_persist,
                         cudaFuncAttributeMaxDynamicSharedMemorySize,
                         GEMM_SMEM_BYTES);

    recur_kernel<<<RECUR_BLOCKS, 256>>>(
        item_table, user_table, memory_init, user_id, seq, seq_length);

    gemm_persist<<<STRIPS * SLOTS, 512, GEMM_SMEM_BYTES>>>(item_table, scores);
}

// round 12
// speedup vs baseline: 1.3791x; 1.3791x over previous
#include <cuda_runtime.h>
#include <cuda_bf16.h>
#include <cstdint>

#define B_      1024
#define L_      50
#define K_      20
#define D_      64
#define NITEMS  100000
#define NUSERS  10000
#define ALPHA   0.2f

#define NT_PAD   12512              // n8-tiles padded to multiple of 16
#define NGROUPS  (NT_PAD / 16)      // 782 groups of 128 cols
#define STRIPS   8
#define SLOTS    18
#define NCTAS    (STRIPS * SLOTS)   // 144

#define NWU4     (NT_PAD * 4 * 32)  // 1601536 uint4 fragments
#define BWARPS   (NCTAS * 8)        // 1152 bfrag warps
#define BSTRIDE  (BWARPS * 32)      // 36864 threads

__device__ float g_pu[B_ * D_];
// B fragments: [nt][j(4)][lane(32)] uint4 (k-steps 2j,2j+1), column-paired
__device__ uint4 g_bfrag[NWU4];                // 25.6 MB
__device__ unsigned g_bar = 0;                 // monotonic ticket barrier

__device__ __forceinline__ uint32_t f2tf32(float x) {
    uint32_t u;
    asm("cvt.rn.tf32.f32 %0, %1;" : "=r"(u) : "f"(x));
    return u;
}
__device__ __forceinline__ uint32_t smem_u32(const void* p) {
    uint32_t a;
    asm("{ .reg .u64 t; cvta.to.shared.u64 t, %1; cvt.u32.u64 %0, t; }"
        : "=r"(a) : "l"(p));
    return a;
}
__device__ __forceinline__ void cp_async16(uint32_t dst, const void* src) {
    asm volatile("cp.async.cg.shared.global [%0], [%1], 16;"
                 :: "r"(dst), "l"(src) : "memory");
}
#define CP_COMMIT() asm volatile("cp.async.commit_group;" ::: "memory")
#define CP_WAIT(n)  asm volatile("cp.async.wait_group %0;" :: "n"(n) : "memory")

__device__ __forceinline__ void mma_tf32(float& c0, float& c1, float& c2, float& c3,
                                         uint32_t a0, uint32_t a1, uint32_t a2, uint32_t a3,
                                         uint32_t b0, uint32_t b1) {
    asm volatile("mma.sync.aligned.m16n8k8.row.col.f32.tf32.tf32.f32 "
                 "{%0,%1,%2,%3}, {%4,%5,%6,%7}, {%8,%9}, {%0,%1,%2,%3};"
                 : "+f"(c0), "+f"(c1), "+f"(c2), "+f"(c3)
                 : "r"(a0), "r"(a1), "r"(a2), "r"(a3), "r"(b0), "r"(b1));
}

__device__ __forceinline__ float tree_sum20(const float* s) {
    float t1[10];
#pragma unroll
    for (int i = 0; i < 10; i++) t1[i] = s[2 * i] + s[2 * i + 1];
    float t2[5];
#pragma unroll
    for (int i = 0; i < 5; i++) t2[i] = t1[2 * i] + t1[2 * i + 1];
    return ((t2[0] + t2[1]) + (t2[2] + t2[3])) + t2[4];
}

#define TILE_U4   2048                       // uint4 per 128-col B group
#define GEMM_SMEM_BYTES (3 * TILE_U4 * 16)   // 96 KB

// ===========================================================================
// Single persistent kernel, 144 CTAs x 512 threads.
// Phase 0 (warp-specialized, no intra-CTA sync):
//   warps 0-7 : recurrence, one batch row each (1152 warps >= 1024 rows)
//   warps 8-15: B fragment transform (scalar gather, column-paired layout)
// Ticket barrier.
// Phase 2: R7 GEMM (A in regs, per-thread cp.async 3-stage ring, STG.128).
// ===========================================================================
__global__ void __launch_bounds__(512, 1)
fused_kernel(const float* __restrict__ item,
             const float* __restrict__ user,
             const float* __restrict__ mem_init,
             const int*   __restrict__ user_id,
             const int*   __restrict__ seq,
             const int*   __restrict__ seq_len,
             float* __restrict__ C)
{
    extern __shared__ uint4 smem[];          // 96 KB B ring (phase 2 only)

    const int tid  = threadIdx.x;
    const int wid  = tid >> 5;
    const int lane = tid & 31;
    const int cta  = blockIdx.x;

    // ======================= PHASE 0 =======================
    if (wid < 8) {
        // ---------------- recurrence: one batch row per warp ----------------
        const int b = cta * 8 + wid;
        if (b < B_) {
            float m0[K_], m1[K_];
            const float* mi = mem_init + (size_t)b * K_ * D_;
#pragma unroll
            for (int k = 0; k < K_; k++) {
                m0[k] = mi[k * D_ + lane];
                m1[k] = mi[k * D_ + lane + 32];
            }

            const int T = seq_len[b];
            const int* sq = seq + b * L_;

            for (int t0 = 0; t0 < T; t0 += 8) {
                int nt = min(8, T - t0);
                float e0[8], e1[8];
#pragma unroll
                for (int i = 0; i < 8; i++) {
                    if (i < nt) {
                        int idx = __ldg(sq + t0 + i);
                        e0[i] = __ldg(item + (size_t)idx * D_ + lane);
                        e1[i] = __ldg(item + (size_t)idx * D_ + lane + 32);
                    }
                }
#pragma unroll
                for (int i = 0; i < 8; i++) {
                    if (i >= nt) break;
                    float s[K_];
#pragma unroll
                    for (int k = 0; k < K_; k++) {
                        float p = fmaf(m0[k], e0[i], m1[k] * e1[i]);
#pragma unroll
                        for (int off = 16; off > 0; off >>= 1)
                            p += __shfl_xor_sync(0xffffffffu, p, off);
                        s[k] = p;
                    }
#pragma unroll
                    for (int k = 0; k < K_; k++) s[k] = __expf(s[k]);
                    float inv = __fdividef(1.f, tree_sum20(s));
                    float er0 = __fdividef(1.f, 1.f + __expf(-e0[i]));
                    float er1 = __fdividef(1.f, 1.f + __expf(-e1[i]));
                    float ex0 = __expf(2.f * e0[i]);
                    float ex1 = __expf(2.f * e1[i]);
                    float ad0 = __fdividef(ex0 - 1.f, ex0 + 1.f);
                    float ad1 = __fdividef(ex1 - 1.f, ex1 + 1.f);
#pragma unroll
                    for (int k = 0; k < K_; k++) {
                        float z = s[k] * inv;
                        m0[k] = m0[k] * (1.f - z * er0) + z * ad0;
                        m1[k] = m1[k] * (1.f - z * er1) + z * ad1;
                    }
                }
            }

            int lidx = __ldg(sq + L_ - 1);
            float l0 = __ldg(item + (size_t)lidx * D_ + lane);
            float l1 = __ldg(item + (size_t)lidx * D_ + lane + 32);
            float s[K_];
#pragma unroll
            for (int k = 0; k < K_; k++) {
                float p = fmaf(m0[k], l0, m1[k] * l1);
#pragma unroll
                for (int off = 16; off > 0; off >>= 1)
                    p += __shfl_xor_sync(0xffffffffu, p, off);
                s[k] = __expf(p);
            }
            float inv = __fdividef(1.f, tree_sum20(s));
            float p0 = 0.f, p1 = 0.f;
#pragma unroll
            for (int k = 0; k < K_; k++) {
                float z = s[k] * inv;
                p0 = fmaf(z, m0[k], p0);
                p1 = fmaf(z, m1[k], p1);
            }
            int uid = __ldg(user_id + b);
            g_pu[b * D_ + lane]      = __ldg(user + (size_t)uid * D_ + lane)      + ALPHA * p0;
            g_pu[b * D_ + lane + 32] = __ldg(user + (size_t)uid * D_ + lane + 32) + ALPHA * p1;
        }
    } else {
        // ---------------- B fragment transform (scalar gather) --------------
        const int gw = cta * 8 + (wid - 8);           // 0..1151
        const int w = lane >> 2;
        const int t = lane & 3;
        for (unsigned u = (unsigned)gw * 32u + lane; u < NWU4; u += BSTRIDE) {
            int j   = (u >> 5) & 3;
            int nt  = u >> 7;
            int par = nt & 1;
            int n   = (nt >> 1) * 16 +
                      ((w & 1) ? (2 * w - 1 + 2 * par) : (2 * w + 2 * par));
            int k0  = j * 16 + t;
            uint4 v = make_uint4(0u, 0u, 0u, 0u);
            if (n < NITEMS) {
                const float* r = item + (size_t)n * 64;
                v.x = f2tf32(__ldg(r + k0));
                v.y = f2tf32(__ldg(r + k0 + 4));
                v.z = f2tf32(__ldg(r + k0 + 8));
                v.w = f2tf32(__ldg(r + k0 + 12));
            }
            g_bfrag[u] = v;
        }
    }

    // ======================= BARRIER =======================
    __threadfence();
    __syncthreads();
    if (tid == 0) {
        unsigned ticket = atomicAdd(&g_bar, 1u);
        unsigned target = (ticket / NCTAS + 1u) * NCTAS;
        while (*(volatile unsigned*)&g_bar < target) { }
    }
    __syncthreads();
    __threadfence();

    // ======================= PHASE 2: GEMM (R7) =======================
    const uint32_t sBb = smem_u32(smem);
    const int wm = wid >> 2;
    const int wn = wid & 3;
    const int g  = lane >> 2;
    const int t2 = lane & 3;

    const int strip = cta & 7;
    const int slot  = cta >> 3;

    uint4 a[2][8];
    {
        const float* pu = g_pu + (size_t)(strip * 128 + wm * 32) * 64;
#pragma unroll
        for (int mi = 0; mi < 2; mi++) {
            int r0 = mi * 16 + g;
#pragma unroll
            for (int ks = 0; ks < 8; ks++) {
                int k0 = ks * 8 + t2;
                a[mi][ks].x = f2tf32(pu[r0 * 64 + k0]);
                a[mi][ks].y = f2tf32(pu[(r0 + 8) * 64 + k0]);
                a[mi][ks].z = f2tf32(pu[r0 * 64 + k0 + 4]);
                a[mi][ks].w = f2tf32(pu[(r0 + 8) * 64 + k0 + 4]);
            }
        }
    }

    const int row_base = strip * 128 + wm * 32;

#pragma unroll
    for (int pf = 0; pf < 2; pf++) {
        int grp = slot + pf * SLOTS;          // always < NGROUPS (max 35)
        const uint4* src = g_bfrag + (size_t)grp * TILE_U4 + tid;
        uint32_t dst = sBb + (uint32_t)(pf * TILE_U4 + tid) * 16u;
#pragma unroll
        for (int r = 0; r < 4; r++)
            cp_async16(dst + r * 512 * 16, src + r * 512);
        CP_COMMIT();
    }

    int iter = 0;
    for (int grp = slot; grp < NGROUPS; grp += SLOTS, iter++) {
        const int buf = iter - (iter / 3) * 3;
        CP_WAIT(1);
        __syncthreads();

        {
            int nxt = grp + 2 * SLOTS;
            if (nxt < NGROUPS) {
                const int pbuf = (buf + 2 >= 3) ? buf - 1 : buf + 2;
                const uint4* src = g_bfrag + (size_t)nxt * TILE_U4 + tid;
                uint32_t dst = sBb + (uint32_t)(pbuf * TILE_U4 + tid) * 16u;
#pragma unroll
                for (int r = 0; r < 4; r++)
                    cp_async16(dst + r * 512 * 16, src + r * 512);
            }
            CP_COMMIT();
        }

        float acc[2][2][2][4];
#pragma unroll
        for (int i = 0; i < 2; i++)
#pragma unroll
            for (int p = 0; p < 2; p++)
#pragma unroll
                for (int q = 0; q < 2; q++)
#pragma unroll
                    for (int r = 0; r < 4; r++) acc[i][p][q][r] = 0.f;

        const uint4* Bs = smem + buf * TILE_U4;
#pragma unroll
        for (int j = 0; j < 4; j++) {
            uint4 b[2][2];
#pragma unroll
            for (int p = 0; p < 2; p++)
#pragma unroll
                for (int q = 0; q < 2; q++)
                    b[p][q] = Bs[((wn * 4 + p * 2 + q) * 4 + j) * 32 + lane];
#pragma unroll
            for (int s = 0; s < 2; s++) {
                const int ks = 2 * j + s;
#pragma unroll
                for (int mi = 0; mi < 2; mi++)
#pragma unroll
                    for (int p = 0; p < 2; p++)
#pragma unroll
                        for (int q = 0; q < 2; q++) {
                            uint32_t b0 = (s == 0) ? b[p][q].x : b[p][q].z;
                            uint32_t b1 = (s == 0) ? b[p][q].y : b[p][q].w;
                            mma_tf32(acc[mi][p][q][0], acc[mi][p][q][1],
                                     acc[mi][p][q][2], acc[mi][p][q][3],
                                     a[mi][ks].x, a[mi][ks].y, a[mi][ks].z, a[mi][ks].w,
                                     b0, b1);
                        }
            }
        }

#pragma unroll
        for (int mi = 0; mi < 2; mi++) {
            int row0 = row_base + mi * 16 + g;
#pragma unroll
            for (int p = 0; p < 2; p++) {
                int base16 = grp * 128 + wn * 32 + p * 16;
                if (base16 < NITEMS) {       // NITEMS % 16 == 0
                    int col = base16 + 4 * t2;
                    __stcs((float4*)(C + (size_t)row0 * NITEMS + col),
                           make_float4(acc[mi][p][0][0], acc[mi][p][0][1],
                                       acc[mi][p][1][0], acc[mi][p][1][1]));
                    __stcs((float4*)(C + (size_t)(row0 + 8) * NITEMS + col),
                           make_float4(acc[mi][p][0][2], acc[mi][p][0][3],
                                       acc[mi][p][1][2], acc[mi][p][1][3]));
                }
            }
        }
    }
}

// ===========================================================================
extern "C" void kernel_launch(void* const* d_in, const int* in_sizes, int n_in,
                              void* d_out, int out_size)
{
    const float* item_table  = (const float*)d_in[0];
    const float* user_table  = (const float*)d_in[1];
    const float* memory_init = (const float*)d_in[2];
    const int*   user_id     = (const int*)d_in[3];
    const int*   seq         = (const int*)d_in[4];
    const int*   seq_length  = (const int*)d_in[5];
    float*       scores      = (float*)d_out;

    cudaFuncSetAttribute(fused_kernel,
                         cudaFuncAttributeMaxDynamicSharedMemorySize,
                         GEMM_SMEM_BYTES);

    fused_kernel<<<NCTAS, 512, GEMM_SMEM_BYTES>>>(
        item_table, user_table, memory_init, user_id, seq, seq_length, scores);
}

// round 13
// speedup vs baseline: 1.4012x; 1.0160x over previous
#include <cuda_runtime.h>
#include <cuda_bf16.h>
#include <cstdint>

#define B_      1024
#define L_      50
#define K_      20
#define D_      64
#define NITEMS  100000
#define NUSERS  10000
#define ALPHA   0.2f

#define NT_PAD   12512              // n8-tiles padded to multiple of 16
#define NGROUPS  (NT_PAD / 16)      // 782 GEMM groups of 128 cols
#define NGRP16   (NT_PAD / 2)       // 6256 transform groups of 16 rows
#define STRIPS   8
#define SLOTS    18
#define NCTAS    (STRIPS * SLOTS)   // 144

__device__ float g_pu[B_ * D_];
// B fragments: [nt][j(4)][lane(32)] uint4 (k-steps 2j,2j+1), column-paired
__device__ uint4 g_bfrag[NT_PAD * 4 * 32];     // 25.6 MB
__device__ unsigned g_bar = 0;                 // monotonic ticket barrier

__device__ __forceinline__ uint32_t f2tf32(float x) {
    uint32_t u;
    asm("cvt.rn.tf32.f32 %0, %1;" : "=r"(u) : "f"(x));
    return u;
}
__device__ __forceinline__ uint32_t smem_u32(const void* p) {
    uint32_t a;
    asm("{ .reg .u64 t; cvta.to.shared.u64 t, %1; cvt.u32.u64 %0, t; }"
        : "=r"(a) : "l"(p));
    return a;
}
__device__ __forceinline__ void cp_async16(uint32_t dst, const void* src) {
    asm volatile("cp.async.cg.shared.global [%0], [%1], 16;"
                 :: "r"(dst), "l"(src) : "memory");
}
// 16B async copy with runtime src-size (0 -> zero-fill)
__device__ __forceinline__ void cp_async16z(uint32_t dst, const void* src,
                                            unsigned sbytes) {
    asm volatile("cp.async.cg.shared.global [%0], [%1], 16, %2;"
                 :: "r"(dst), "l"(src), "r"(sbytes) : "memory");
}
#define CP_COMMIT() asm volatile("cp.async.commit_group;" ::: "memory")
#define CP_WAIT(n)  asm volatile("cp.async.wait_group %0;" :: "n"(n) : "memory")
#define BARX(id, n) asm volatile("bar.sync %0, %1;" :: "r"(id), "r"(n) : "memory")

__device__ __forceinline__ void mma_tf32(float& c0, float& c1, float& c2, float& c3,
                                         uint32_t a0, uint32_t a1, uint32_t a2, uint32_t a3,
                                         uint32_t b0, uint32_t b1) {
    asm volatile("mma.sync.aligned.m16n8k8.row.col.f32.tf32.tf32.f32 "
                 "{%0,%1,%2,%3}, {%4,%5,%6,%7}, {%8,%9}, {%0,%1,%2,%3};"
                 : "+f"(c0), "+f"(c1), "+f"(c2), "+f"(c3)
                 : "r"(a0), "r"(a1), "r"(a2), "r"(a3), "r"(b0), "r"(b1));
}

__device__ __forceinline__ float tree_sum20(const float* s) {
    float t1[10];
#pragma unroll
    for (int i = 0; i < 10; i++) t1[i] = s[2 * i] + s[2 * i + 1];
    float t2[5];
#pragma unroll
    for (int i = 0; i < 5; i++) t2[i] = t1[2 * i] + t1[2 * i + 1];
    return ((t2[0] + t2[1]) + (t2[2] + t2[3])) + t2[4];
}

#define TILE_U4   2048                       // uint4 per 128-col B group
#define GEMM_SMEM_BYTES (3 * TILE_U4 * 16)   // 96 KB

// ===========================================================================
// Single persistent kernel, 144 CTAs x 512 threads.
// Phase 0 (warp-specialized):
//   warps 0-7 : recurrence, one batch row each (1152 warps >= 1024 rows)
//   warps 8-15: B fragment transform — team-staged through double-buffered
//               smem (cp.async in, conflict-free LDS gather, STG.128 out),
//               synced by NAMED barrier 1 (256 threads) only.
// Ticket barrier.  Phase 2: R7 GEMM (A in regs, cp.async 3-stage ring).
// ===========================================================================
__global__ void __launch_bounds__(512, 1)
fused_kernel(const float* __restrict__ item,
             const float* __restrict__ user,
             const float* __restrict__ mem_init,
             const int*   __restrict__ user_id,
             const int*   __restrict__ seq,
             const int*   __restrict__ seq_len,
             float* __restrict__ C)
{
    extern __shared__ uint4 smem[];          // 96 KB: phase0 stage / phase2 ring

    const int tid  = threadIdx.x;
    const int wid  = tid >> 5;
    const int lane = tid & 31;
    const int cta  = blockIdx.x;

    // ======================= PHASE 0 =======================
    if (wid < 8) {
        // ---------------- recurrence: one batch row per warp ----------------
        const int b = cta * 8 + wid;
        if (b < B_) {
            float m0[K_], m1[K_];
            const float* mi = mem_init + (size_t)b * K_ * D_;
#pragma unroll
            for (int k = 0; k < K_; k++) {
                m0[k] = mi[k * D_ + lane];
                m1[k] = mi[k * D_ + lane + 32];
            }

            const int T = seq_len[b];
            const int* sq = seq + b * L_;

            for (int t0 = 0; t0 < T; t0 += 8) {
                int nt = min(8, T - t0);
                float e0[8], e1[8];
#pragma unroll
                for (int i = 0; i < 8; i++) {
                    if (i < nt) {
                        int idx = __ldg(sq + t0 + i);
                        e0[i] = __ldg(item + (size_t)idx * D_ + lane);
                        e1[i] = __ldg(item + (size_t)idx * D_ + lane + 32);
                    }
                }
#pragma unroll
                for (int i = 0; i < 8; i++) {
                    if (i >= nt) break;
                    float s[K_];
#pragma unroll
                    for (int k = 0; k < K_; k++) {
                        float p = fmaf(m0[k], e0[i], m1[k] * e1[i]);
#pragma unroll
                        for (int off = 16; off > 0; off >>= 1)
                            p += __shfl_xor_sync(0xffffffffu, p, off);
                        s[k] = p;
                    }
#pragma unroll
                    for (int k = 0; k < K_; k++) s[k] = __expf(s[k]);
                    float inv = __fdividef(1.f, tree_sum20(s));
                    float er0 = __fdividef(1.f, 1.f + __expf(-e0[i]));
                    float er1 = __fdividef(1.f, 1.f + __expf(-e1[i]));
                    float ex0 = __expf(2.f * e0[i]);
                    float ex1 = __expf(2.f * e1[i]);
                    float ad0 = __fdividef(ex0 - 1.f, ex0 + 1.f);
                    float ad1 = __fdividef(ex1 - 1.f, ex1 + 1.f);
#pragma unroll
                    for (int k = 0; k < K_; k++) {
                        float z = s[k] * inv;
                        m0[k] = m0[k] * (1.f - z * er0) + z * ad0;
                        m1[k] = m1[k] * (1.f - z * er1) + z * ad1;
                    }
                }
            }

            int lidx = __ldg(sq + L_ - 1);
            float l0 = __ldg(item + (size_t)lidx * D_ + lane);
            float l1 = __ldg(item + (size_t)lidx * D_ + lane + 32);
            float s[K_];
#pragma unroll
            for (int k = 0; k < K_; k++) {
                float p = fmaf(m0[k], l0, m1[k] * l1);
#pragma unroll
                for (int off = 16; off > 0; off >>= 1)
                    p += __shfl_xor_sync(0xffffffffu, p, off);
                s[k] = __expf(p);
            }
            float inv = __fdividef(1.f, tree_sum20(s));
            float p0 = 0.f, p1 = 0.f;
#pragma unroll
            for (int k = 0; k < K_; k++) {
                float z = s[k] * inv;
                p0 = fmaf(z, m0[k], p0);
                p1 = fmaf(z, m1[k], p1);
            }
            int uid = __ldg(user_id + b);
            g_pu[b * D_ + lane]      = __ldg(user + (size_t)uid * D_ + lane)      + ALPHA * p0;
            g_pu[b * D_ + lane + 32] = __ldg(user + (size_t)uid * D_ + lane + 32) + ALPHA * p1;
        }
    } else {
        // ------- B fragment transform: team of 8 warps, staged via smem ------
        // stage buffers: 2 x (16 rows x 68 floats) at start of dynamic smem
        float* const stage = (float*)smem;           // 2 * 4352 B
        const uint32_t stage_b = smem_u32(smem);
        const int tid2 = tid - 256;                  // 0..255

        const int srow = tid2 >> 4;                  // staging: row 0..15
        const int sf4  = tid2 & 15;                  // float4 within row

        const int j    = (tid2 >> 5) & 3;
        const int par  = tid2 >> 7;                  // which nt of the group
        const int w    = lane >> 2;
        const int t    = lane & 3;
        const int nl   = (w & 1) ? (2 * w - 1 + 2 * par) : (2 * w + 2 * par);

        // prologue: stage first group into buffer 0
        {
            int n = cta * 16 + srow;                 // group g0 = cta
            unsigned sb = (n < NITEMS) ? 16u : 0u;
            cp_async16z(stage_b + (srow * 68 + sf4 * 4) * 4,
                        item + (size_t)n * 64 + sf4 * 4, sb);
            CP_COMMIT();
        }

        int it = 0;
        for (int gg = cta; gg < NGRP16; gg += NCTAS, it++) {
            const int cur = it & 1;
            // issue next group's copy into the other buffer
            {
                int gn = gg + NCTAS;
                if (gn < NGRP16) {
                    int n = gn * 16 + srow;
                    unsigned sb = (n < NITEMS) ? 16u : 0u;
                    cp_async16z(stage_b + ((cur ^ 1) * 1088 + srow * 68 + sf4 * 4) * 4,
                                item + (size_t)n * 64 + sf4 * 4, sb);
                }
                CP_COMMIT();
            }
            CP_WAIT(1);              // current buffer's copies (all threads') issued
            BARX(1, 256);            // ... and visible to the whole team

            const float* st = stage + cur * 1088;
            uint4 v;
            v.x = f2tf32(st[nl * 68 + (j * 4 + 0) * 4 + t]);
            v.y = f2tf32(st[nl * 68 + (j * 4 + 1) * 4 + t]);
            v.z = f2tf32(st[nl * 68 + (j * 4 + 2) * 4 + t]);
            v.w = f2tf32(st[nl * 68 + (j * 4 + 3) * 4 + t]);
            g_bfrag[(size_t)gg * 256 + tid2] = v;

            BARX(1, 256);            // reads done before buffer reused (it+1 writes cur)
        }
    }

    // ======================= BARRIER =======================
    __threadfence();
    __syncthreads();
    if (tid == 0) {
        unsigned ticket = atomicAdd(&g_bar, 1u);
        unsigned target = (ticket / NCTAS + 1u) * NCTAS;
        while (*(volatile unsigned*)&g_bar < target) { }
    }
    __syncthreads();
    __threadfence();

    // ======================= PHASE 2: GEMM (R7) =======================
    const uint32_t sBb = smem_u32(smem);
    const int wm = wid >> 2;
    const int wn = wid & 3;
    const int g  = lane >> 2;
    const int t2 = lane & 3;

    const int strip = cta & 7;
    const int slot  = cta >> 3;

    uint4 a[2][8];
    {
        const float* pu = g_pu + (size_t)(strip * 128 + wm * 32) * 64;
#pragma unroll
        for (int mi = 0; mi < 2; mi++) {
            int r0 = mi * 16 + g;
#pragma unroll
            for (int ks = 0; ks < 8; ks++) {
                int k0 = ks * 8 + t2;
                a[mi][ks].x = f2tf32(pu[r0 * 64 + k0]);
                a[mi][ks].y = f2tf32(pu[(r0 + 8) * 64 + k0]);
                a[mi][ks].z = f2tf32(pu[r0 * 64 + k0 + 4]);
                a[mi][ks].w = f2tf32(pu[(r0 + 8) * 64 + k0 + 4]);
            }
        }
    }

    const int row_base = strip * 128 + wm * 32;

#pragma unroll
    for (int pf = 0; pf < 2; pf++) {
        int grp = slot + pf * SLOTS;          // always < NGROUPS (max 35)
        const uint4* src = g_bfrag + (size_t)grp * TILE_U4 + tid;
        uint32_t dst = sBb + (uint32_t)(pf * TILE_U4 + tid) * 16u;
#pragma unroll
        for (int r = 0; r < 4; r++)
            cp_async16(dst + r * 512 * 16, src + r * 512);
        CP_COMMIT();
    }

    int iter = 0;
    for (int grp = slot; grp < NGROUPS; grp += SLOTS, iter++) {
        const int buf = iter - (iter / 3) * 3;
        CP_WAIT(1);
        __syncthreads();

        {
            int nxt = grp + 2 * SLOTS;
            if (nxt < NGROUPS) {
                const int pbuf = (buf + 2 >= 3) ? buf - 1 : buf + 2;
                const uint4* src = g_bfrag + (size_t)nxt * TILE_U4 + tid;
                uint32_t dst = sBb + (uint32_t)(pbuf * TILE_U4 + tid) * 16u;
#pragma unroll
                for (int r = 0; r < 4; r++)
                    cp_async16(dst + r * 512 * 16, src + r * 512);
            }
            CP_COMMIT();
        }

        float acc[2][2][2][4];
#pragma unroll
        for (int i = 0; i < 2; i++)
#pragma unroll
            for (int p = 0; p < 2; p++)
#pragma unroll
                for (int q = 0; q < 2; q++)
#pragma unroll
                    for (int r = 0; r < 4; r++) acc[i][p][q][r] = 0.f;

        const uint4* Bs = smem + buf * TILE_U4;
#pragma unroll
        for (int j = 0; j < 4; j++) {
            uint4 b[2][2];
#pragma unroll
            for (int p = 0; p < 2; p++)
#pragma unroll
                for (int q = 0; q < 2; q++)
                    b[p][q] = Bs[((wn * 4 + p * 2 + q) * 4 + j) * 32 + lane];
#pragma unroll
            for (int s = 0; s < 2; s++) {
                const int ks = 2 * j + s;
#pragma unroll
                for (int mi = 0; mi < 2; mi++)
#pragma unroll
                    for (int p = 0; p < 2; p++)
#pragma unroll
                        for (int q = 0; q < 2; q++) {
                            uint32_t b0 = (s == 0) ? b[p][q].x : b[p][q].z;
                            uint32_t b1 = (s == 0) ? b[p][q].y : b[p][q].w;
                            mma_tf32(acc[mi][p][q][0], acc[mi][p][q][1],
                                     acc[mi][p][q][2], acc[mi][p][q][3],
                                     a[mi][ks].x, a[mi][ks].y, a[mi][ks].z, a[mi][ks].w,
                                     b0, b1);
                        }
            }
        }

#pragma unroll
        for (int mi = 0; mi < 2; mi++) {
            int row0 = row_base + mi * 16 + g;
#pragma unroll
            for (int p = 0; p < 2; p++) {
                int base16 = grp * 128 + wn * 32 + p * 16;
                if (base16 < NITEMS) {       // NITEMS % 16 == 0
                    int col = base16 + 4 * t2;
                    __stcs((float4*)(C + (size_t)row0 * NITEMS + col),
                           make_float4(acc[mi][p][0][0], acc[mi][p][0][1],
                                       acc[mi][p][1][0], acc[mi][p][1][1]));
                    __stcs((float4*)(C + (size_t)(row0 + 8) * NITEMS + col),
                           make_float4(acc[mi][p][0][2], acc[mi][p][0][3],
                                       acc[mi][p][1][2], acc[mi][p][1][3]));
                }
            }
        }
    }
}

// ===========================================================================
extern "C" void kernel_launch(void* const* d_in, const int* in_sizes, int n_in,
                              void* d_out, int out_size)
{
    const float* item_table  = (const float*)d_in[0];
    const float* user_table  = (const float*)d_in[1];
    const float* memory_init = (const float*)d_in[2];
    const int*   user_id     = (const int*)d_in[3];
    const int*   seq         = (const int*)d_in[4];
    const int*   seq_length  = (const int*)d_in[5];
    float*       scores      = (float*)d_out;

    cudaFuncSetAttribute(fused_kernel,
                         cudaFuncAttributeMaxDynamicSharedMemorySize,
                         GEMM_SMEM_BYTES);

    fused_kernel<<<NCTAS, 512, GEMM_SMEM_BYTES>>>(
        item_table, user_table, memory_init, user_id, seq, seq_length, scores);
}

// round 14
// speedup vs baseline: 1.5519x; 1.1075x over previous
#include <cuda_runtime.h>
#include <cuda_bf16.h>
#include <cstdint>

#define B_      1024
#define L_      50
#define K_      20
#define D_      64
#define NITEMS  100000
#define NUSERS  10000
#define ALPHA   0.2f

#define NT_PAD   12512              // n8-tiles padded to multiple of 16
#define NGROUPS  (NT_PAD / 16)      // 782 GEMM groups of 128 cols
#define NGRP16   (NT_PAD / 2)       // 6256 transform groups of 16 rows
#define STRIPS   8
#define SLOTS    18
#define NCTAS    (STRIPS * SLOTS)   // 144

__device__ float g_pu[B_ * D_];
// B fragments: [nt][j(4)][lane(32)] uint4 (k-steps 2j,2j+1), column-paired
__device__ uint4 g_bfrag[NT_PAD * 4 * 32];     // 25.6 MB
__device__ unsigned g_bar = 0;                 // monotonic ticket barrier

__device__ __forceinline__ uint32_t f2tf32(float x) {
    uint32_t u;
    asm("cvt.rn.tf32.f32 %0, %1;" : "=r"(u) : "f"(x));
    return u;
}
__device__ __forceinline__ uint32_t smem_u32(const void* p) {
    uint32_t a;
    asm("{ .reg .u64 t; cvta.to.shared.u64 t, %1; cvt.u32.u64 %0, t; }"
        : "=r"(a) : "l"(p));
    return a;
}
__device__ __forceinline__ void cp_async16(uint32_t dst, const void* src) {
    asm volatile("cp.async.cg.shared.global [%0], [%1], 16;"
                 :: "r"(dst), "l"(src) : "memory");
}
__device__ __forceinline__ void cp_async16z(uint32_t dst, const void* src,
                                            unsigned sbytes) {
    asm volatile("cp.async.cg.shared.global [%0], [%1], 16, %2;"
                 :: "r"(dst), "l"(src), "r"(sbytes) : "memory");
}
#define CP_COMMIT() asm volatile("cp.async.commit_group;" ::: "memory")
#define CP_WAIT(n)  asm volatile("cp.async.wait_group %0;" :: "n"(n) : "memory")
#define BARX(id, n) asm volatile("bar.sync %0, %1;" :: "r"(id), "r"(n) : "memory")

__device__ __forceinline__ void mma_tf32(float& c0, float& c1, float& c2, float& c3,
                                         uint32_t a0, uint32_t a1, uint32_t a2, uint32_t a3,
                                         uint32_t b0, uint32_t b1) {
    asm volatile("mma.sync.aligned.m16n8k8.row.col.f32.tf32.tf32.f32 "
                 "{%0,%1,%2,%3}, {%4,%5,%6,%7}, {%8,%9}, {%0,%1,%2,%3};"
                 : "+f"(c0), "+f"(c1), "+f"(c2), "+f"(c3)
                 : "r"(a0), "r"(a1), "r"(a2), "r"(a3), "r"(b0), "r"(b1));
}

// ---------------------------------------------------------------------------
// Multi-value reduce-and-transpose: lane provides partials v[k] (k<20, rest 0).
// Returns: lane l holds sum_{lanes} v[l]  (l < 20; lanes 20-31 hold 0).
// 50 SHFLs, depth 5 (vs 100 SHFLs, 20 x depth-5 chains).
// ---------------------------------------------------------------------------
__device__ __forceinline__ float xpose_reduce20(const float* v, int lane) {
    const unsigned FM = 0xffffffffu;
    float h16[16];
    const bool b4 = (lane & 16) != 0;
#pragma unroll
    for (int i = 0; i < 16; i++) {
        float t0 = v[i] + __shfl_xor_sync(FM, v[i], 16);
        float t1 = (i < 4) ? (v[16 + i] + __shfl_xor_sync(FM, v[16 + i], 16)) : 0.f;
        h16[i] = b4 ? t1 : t0;
    }
    float h8[8];
    const bool b3 = (lane & 8) != 0;
#pragma unroll
    for (int i = 0; i < 8; i++) {
        float t0 = h16[i] + __shfl_xor_sync(FM, h16[i], 8);
        float t1 = h16[8 + i] + __shfl_xor_sync(FM, h16[8 + i], 8);
        h8[i] = b3 ? t1 : t0;
    }
    float h4[4];
    const bool b2 = (lane & 4) != 0;
#pragma unroll
    for (int i = 0; i < 4; i++) {
        float t0 = h8[i] + __shfl_xor_sync(FM, h8[i], 4);
        float t1 = h8[4 + i] + __shfl_xor_sync(FM, h8[4 + i], 4);
        h4[i] = b2 ? t1 : t0;
    }
    float h2[2];
    const bool b1 = (lane & 2) != 0;
#pragma unroll
    for (int i = 0; i < 2; i++) {
        float t0 = h2[0];  // placeholder to keep unroll shape
        (void)t0;
        float u0 = h4[i] + __shfl_xor_sync(FM, h4[i], 2);
        float u1 = h4[2 + i] + __shfl_xor_sync(FM, h4[2 + i], 2);
        h2[i] = b1 ? u1 : u0;
    }
    const bool b0 = (lane & 1) != 0;
    float u0 = h2[0] + __shfl_xor_sync(FM, h2[0], 1);
    float u1 = h2[1] + __shfl_xor_sync(FM, h2[1], 1);
    return b0 ? u1 : u0;
}

#define TILE_U4   2048                       // uint4 per 128-col B group
#define GEMM_SMEM_BYTES (3 * TILE_U4 * 16)   // 96 KB

// ===========================================================================
// Single persistent kernel, 144 CTAs x 512 threads.
// Phase 0 (warp-specialized):
//   warps 0-7 : recurrence (transpose-reduce softmax, 2-FMA update)
//   warps 8-15: B fragment transform via double-buffered smem stage
// Ticket barrier.  Phase 2: R7 GEMM (A in regs, cp.async 3-stage ring).
// ===========================================================================
__global__ void __launch_bounds__(512, 1)
fused_kernel(const float* __restrict__ item,
             const float* __restrict__ user,
             const float* __restrict__ mem_init,
             const int*   __restrict__ user_id,
             const int*   __restrict__ seq,
             const int*   __restrict__ seq_len,
             float* __restrict__ C)
{
    extern __shared__ uint4 smem[];          // 96 KB: phase0 stage / phase2 ring
    const unsigned FM = 0xffffffffu;

    const int tid  = threadIdx.x;
    const int wid  = tid >> 5;
    const int lane = tid & 31;
    const int cta  = blockIdx.x;

    // ======================= PHASE 0 =======================
    if (wid < 8) {
        // ---------------- recurrence: one batch row per warp ----------------
        const int b = cta * 8 + wid;
        if (b < B_) {
            float m0[K_], m1[K_];
            const float* mi = mem_init + (size_t)b * K_ * D_;
#pragma unroll
            for (int k = 0; k < K_; k++) {
                m0[k] = mi[k * D_ + lane];
                m1[k] = mi[k * D_ + lane + 32];
            }

            const int T = seq_len[b];
            const int* sq = seq + b * L_;

            for (int t0 = 0; t0 < T; t0 += 8) {
                int nt = min(8, T - t0);
                float e0[8], e1[8];
#pragma unroll
                for (int i = 0; i < 8; i++) {
                    if (i < nt) {
                        int idx = __ldg(sq + t0 + i);
                        e0[i] = __ldg(item + (size_t)idx * D_ + lane);
                        e1[i] = __ldg(item + (size_t)idx * D_ + lane + 32);
                    }
                }
#pragma unroll
                for (int i = 0; i < 8; i++) {
                    if (i >= nt) break;
                    // partial dots for all 20 slots
                    float v[20];
#pragma unroll
                    for (int k = 0; k < K_; k++)
                        v[k] = fmaf(m0[k], e0[i], m1[k] * e1[i]);
                    float pad[32];
#pragma unroll
                    for (int k = 0; k < 20; k++) pad[k] = v[k];
#pragma unroll
                    for (int k = 20; k < 32; k++) pad[k] = 0.f;
                    float sk = xpose_reduce20(pad, lane);   // lane k holds s_k

                    // softmax (no max-sub: |s| small), exp only in owner lane
                    float es = (lane < K_) ? __expf(sk) : 0.f;
                    float sum = es;
#pragma unroll
                    for (int off = 16; off > 0; off >>= 1)
                        sum += __shfl_xor_sync(FM, sum, off);
                    float z_own = es * __fdividef(1.f, sum);

                    // erase/add gates via one exp each
                    float ex0 = __expf(-e0[i]);
                    float ex1 = __expf(-e1[i]);
                    float er0 = __fdividef(1.f, 1.f + ex0);
                    float er1 = __fdividef(1.f, 1.f + ex1);
                    float q0  = ex0 * ex0;
                    float q1  = ex1 * ex1;
                    float ad0 = __fdividef(1.f - q0, 1.f + q0);
                    float ad1 = __fdividef(1.f - q1, 1.f + q1);

                    // m' = m + z*(ad - m*er)   (2 FMA per element)
#pragma unroll
                    for (int k = 0; k < K_; k++) {
                        float z = __shfl_sync(FM, z_own, k);
                        m0[k] = fmaf(z, fmaf(-m0[k], er0, ad0), m0[k]);
                        m1[k] = fmaf(z, fmaf(-m1[k], er1, ad1), m1[k]);
                    }
                }
            }

            // final attention with last item
            int lidx = __ldg(sq + L_ - 1);
            float l0 = __ldg(item + (size_t)lidx * D_ + lane);
            float l1 = __ldg(item + (size_t)lidx * D_ + lane + 32);
            float pad[32];
#pragma unroll
            for (int k = 0; k < K_; k++)
                pad[k] = fmaf(m0[k], l0, m1[k] * l1);
#pragma unroll
            for (int k = 20; k < 32; k++) pad[k] = 0.f;
            float sk = xpose_reduce20(pad, lane);
            float es = (lane < K_) ? __expf(sk) : 0.f;
            float sum = es;
#pragma unroll
            for (int off = 16; off > 0; off >>= 1)
                sum += __shfl_xor_sync(FM, sum, off);
            float z_own = es * __fdividef(1.f, sum);

            float p0 = 0.f, p1 = 0.f;
#pragma unroll
            for (int k = 0; k < K_; k++) {
                float z = __shfl_sync(FM, z_own, k);
                p0 = fmaf(z, m0[k], p0);
                p1 = fmaf(z, m1[k], p1);
            }
            int uid = __ldg(user_id + b);
            g_pu[b * D_ + lane]      = __ldg(user + (size_t)uid * D_ + lane)      + ALPHA * p0;
            g_pu[b * D_ + lane + 32] = __ldg(user + (size_t)uid * D_ + lane + 32) + ALPHA * p1;
        }
    } else {
        // ------- B fragment transform: team of 8 warps, staged via smem ------
        float* const stage = (float*)smem;           // 2 x 1088 floats
        const uint32_t stage_b = smem_u32(smem);
        const int tid2 = tid - 256;                  // 0..255

        const int srow = tid2 >> 4;
        const int sf4  = tid2 & 15;

        const int j    = (tid2 >> 5) & 3;
        const int par  = tid2 >> 7;
        const int w    = lane >> 2;
        const int t    = lane & 3;
        const int nl   = (w & 1) ? (2 * w - 1 + 2 * par) : (2 * w + 2 * par);

        {
            int n = cta * 16 + srow;
            unsigned sb = (n < NITEMS) ? 16u : 0u;
            cp_async16z(stage_b + (srow * 68 + sf4 * 4) * 4,
                        item + (size_t)n * 64 + sf4 * 4, sb);
            CP_COMMIT();
        }

        int it = 0;
        for (int gg = cta; gg < NGRP16; gg += NCTAS, it++) {
            const int cur = it & 1;
            {
                int gn = gg + NCTAS;
                if (gn < NGRP16) {
                    int n = gn * 16 + srow;
                    unsigned sb = (n < NITEMS) ? 16u : 0u;
                    cp_async16z(stage_b + ((cur ^ 1) * 1088 + srow * 68 + sf4 * 4) * 4,
                                item + (size_t)n * 64 + sf4 * 4, sb);
                }
                CP_COMMIT();
            }
            CP_WAIT(1);
            BARX(1, 256);

            const float* st = stage + cur * 1088;
            uint4 v;
            v.x = f2tf32(st[nl * 68 + (j * 4 + 0) * 4 + t]);
            v.y = f2tf32(st[nl * 68 + (j * 4 + 1) * 4 + t]);
            v.z = f2tf32(st[nl * 68 + (j * 4 + 2) * 4 + t]);
            v.w = f2tf32(st[nl * 68 + (j * 4 + 3) * 4 + t]);
            g_bfrag[(size_t)gg * 256 + tid2] = v;

            BARX(1, 256);
        }
    }

    // ======================= BARRIER =======================
    __threadfence();
    __syncthreads();
    if (tid == 0) {
        unsigned ticket = atomicAdd(&g_bar, 1u);
        unsigned target = (ticket / NCTAS + 1u) * NCTAS;
        while (*(volatile unsigned*)&g_bar < target) { }
    }
    __syncthreads();
    __threadfence();

    // ======================= PHASE 2: GEMM (R7) =======================
    const uint32_t sBb = smem_u32(smem);
    const int wm = wid >> 2;
    const int wn = wid & 3;
    const int g  = lane >> 2;
    const int t2 = lane & 3;

    const int strip = cta & 7;
    const int slot  = cta >> 3;

    uint4 a[2][8];
    {
        const float* pu = g_pu + (size_t)(strip * 128 + wm * 32) * 64;
#pragma unroll
        for (int mi = 0; mi < 2; mi++) {
            int r0 = mi * 16 + g;
#pragma unroll
            for (int ks = 0; ks < 8; ks++) {
                int k0 = ks * 8 + t2;
                a[mi][ks].x = f2tf32(pu[r0 * 64 + k0]);
                a[mi][ks].y = f2tf32(pu[(r0 + 8) * 64 + k0]);
                a[mi][ks].z = f2tf32(pu[r0 * 64 + k0 + 4]);
                a[mi][ks].w = f2tf32(pu[(r0 + 8) * 64 + k0 + 4]);
            }
        }
    }

    const int row_base = strip * 128 + wm * 32;

#pragma unroll
    for (int pf = 0; pf < 2; pf++) {
        int grp = slot + pf * SLOTS;
        const uint4* src = g_bfrag + (size_t)grp * TILE_U4 + tid;
        uint32_t dst = sBb + (uint32_t)(pf * TILE_U4 + tid) * 16u;
#pragma unroll
        for (int r = 0; r < 4; r++)
            cp_async16(dst + r * 512 * 16, src + r * 512);
        CP_COMMIT();
    }

    int iter = 0;
    for (int grp = slot; grp < NGROUPS; grp += SLOTS, iter++) {
        const int buf = iter - (iter / 3) * 3;
        CP_WAIT(1);
        __syncthreads();

        {
            int nxt = grp + 2 * SLOTS;
            if (nxt < NGROUPS) {
                const int pbuf = (buf + 2 >= 3) ? buf - 1 : buf + 2;
                const uint4* src = g_bfrag + (size_t)nxt * TILE_U4 + tid;
                uint32_t dst = sBb + (uint32_t)(pbuf * TILE_U4 + tid) * 16u;
#pragma unroll
                for (int r = 0; r < 4; r++)
                    cp_async16(dst + r * 512 * 16, src + r * 512);
            }
            CP_COMMIT();
        }

        float acc[2][2][2][4];
#pragma unroll
        for (int i = 0; i < 2; i++)
#pragma unroll
            for (int p = 0; p < 2; p++)
#pragma unroll
                for (int q = 0; q < 2; q++)
#pragma unroll
                    for (int r = 0; r < 4; r++) acc[i][p][q][r] = 0.f;

        const uint4* Bs = smem + buf * TILE_U4;
#pragma unroll
        for (int j = 0; j < 4; j++) {
            uint4 b[2][2];
#pragma unroll
            for (int p = 0; p < 2; p++)
#pragma unroll
                for (int q = 0; q < 2; q++)
                    b[p][q] = Bs[((wn * 4 + p * 2 + q) * 4 + j) * 32 + lane];
#pragma unroll
            for (int s = 0; s < 2; s++) {
                const int ks = 2 * j + s;
#pragma unroll
                for (int mi = 0; mi < 2; mi++)
#pragma unroll
                    for (int p = 0; p < 2; p++)
#pragma unroll
                        for (int q = 0; q < 2; q++) {
                            uint32_t b0 = (s == 0) ? b[p][q].x : b[p][q].z;
                            uint32_t b1 = (s == 0) ? b[p][q].y : b[p][q].w;
                            mma_tf32(acc[mi][p][q][0], acc[mi][p][q][1],
                                     acc[mi][p][q][2], acc[mi][p][q][3],
                                     a[mi][ks].x, a[mi][ks].y, a[mi][ks].z, a[mi][ks].w,
                                     b0, b1);
                        }
            }
        }

#pragma unroll
        for (int mi = 0; mi < 2; mi++) {
            int row0 = row_base + mi * 16 + g;
#pragma unroll
            for (int p = 0; p < 2; p++) {
                int base16 = grp * 128 + wn * 32 + p * 16;
                if (base16 < NITEMS) {       // NITEMS % 16 == 0
                    int col = base16 + 4 * t2;
                    __stcs((float4*)(C + (size_t)row0 * NITEMS + col),
                           make_float4(acc[mi][p][0][0], acc[mi][p][0][1],
                                       acc[mi][p][1][0], acc[mi][p][1][1]));
                    __stcs((float4*)(C + (size_t)(row0 + 8) * NITEMS + col),
                           make_float4(acc[mi][p][0][2], acc[mi][p][0][3],
                                       acc[mi][p][1][2], acc[mi][p][1][3]));
                }
            }
        }
    }
}

// ===========================================================================
extern "C" void kernel_launch(void* const* d_in, const int* in_sizes, int n_in,
                              void* d_out, int out_size)
{
    const float* item_table  = (const float*)d_in[0];
    const float* user_table  = (const float*)d_in[1];
    const float* memory_init = (const float*)d_in[2];
    const int*   user_id     = (const int*)d_in[3];
    const int*   seq         = (const int*)d_in[4];
    const int*   seq_length  = (const int*)d_in[5];
    float*       scores      = (float*)d_out;

    cudaFuncSetAttribute(fused_kernel,
                         cudaFuncAttributeMaxDynamicSharedMemorySize,
                         GEMM_SMEM_BYTES);

    fused_kernel<<<NCTAS, 512, GEMM_SMEM_BYTES>>>(
        item_table, user_table, memory_init, user_id, seq, seq_length, scores);
}

// round 15
// speedup vs baseline: 1.6859x; 1.0864x over previous
#include <cuda_runtime.h>
#include <cuda_bf16.h>
#include <cstdint>

#define B_      1024
#define L_      50
#define K_      20
#define D_      64
#define NITEMS  100000
#define NUSERS  10000
#define ALPHA   0.2f

#define NT_PAD   12512              // n8-tiles padded to multiple of 16
#define NGROUPS  (NT_PAD / 8)       // 1564 GEMM groups of 64 cols
#define NGRP16   (NT_PAD / 2)       // 6256 transform groups of 16 rows
#define STRIPS   8
#define SLOTS    36
#define NCTAS    (STRIPS * SLOTS)   // 288 CTAs, 2/SM, one wave

__device__ float g_pu[B_ * D_];
// B fragments: [nt][j(4)][lane(32)] uint4 (k-steps 2j,2j+1), column-paired
__device__ uint4 g_bfrag[NT_PAD * 4 * 32];     // 25.6 MB
__device__ unsigned g_bar = 0;                 // monotonic ticket barrier

__device__ __forceinline__ uint32_t f2tf32(float x) {
    uint32_t u;
    asm("cvt.rn.tf32.f32 %0, %1;" : "=r"(u) : "f"(x));
    return u;
}
__device__ __forceinline__ uint32_t smem_u32(const void* p) {
    uint32_t a;
    asm("{ .reg .u64 t; cvta.to.shared.u64 t, %1; cvt.u32.u64 %0, t; }"
        : "=r"(a) : "l"(p));
    return a;
}
__device__ __forceinline__ void cp_async16(uint32_t dst, const void* src) {
    asm volatile("cp.async.cg.shared.global [%0], [%1], 16;"
                 :: "r"(dst), "l"(src) : "memory");
}
__device__ __forceinline__ void cp_async16z(uint32_t dst, const void* src,
                                            unsigned sbytes) {
    asm volatile("cp.async.cg.shared.global [%0], [%1], 16, %2;"
                 :: "r"(dst), "l"(src), "r"(sbytes) : "memory");
}
#define CP_COMMIT() asm volatile("cp.async.commit_group;" ::: "memory")
#define CP_WAIT(n)  asm volatile("cp.async.wait_group %0;" :: "n"(n) : "memory")
#define BARX(id, n) asm volatile("bar.sync %0, %1;" :: "r"(id), "r"(n) : "memory")

__device__ __forceinline__ void mma_tf32(float& c0, float& c1, float& c2, float& c3,
                                         uint32_t a0, uint32_t a1, uint32_t a2, uint32_t a3,
                                         uint32_t b0, uint32_t b1) {
    asm volatile("mma.sync.aligned.m16n8k8.row.col.f32.tf32.tf32.f32 "
                 "{%0,%1,%2,%3}, {%4,%5,%6,%7}, {%8,%9}, {%0,%1,%2,%3};"
                 : "+f"(c0), "+f"(c1), "+f"(c2), "+f"(c3)
                 : "r"(a0), "r"(a1), "r"(a2), "r"(a3), "r"(b0), "r"(b1));
}

// ---------------------------------------------------------------------------
// Multi-value reduce-and-transpose (R14): lane l ends with sum over lanes of
// v[l] for l<20.  50 SHFLs, depth 5.
// ---------------------------------------------------------------------------
__device__ __forceinline__ float xpose_reduce20(const float* v, int lane) {
    const unsigned FM = 0xffffffffu;
    float h16[16];
    const bool b4 = (lane & 16) != 0;
#pragma unroll
    for (int i = 0; i < 16; i++) {
        float t0 = v[i] + __shfl_xor_sync(FM, v[i], 16);
        float t1 = (i < 4) ? (v[16 + i] + __shfl_xor_sync(FM, v[16 + i], 16)) : 0.f;
        h16[i] = b4 ? t1 : t0;
    }
    float h8[8];
    const bool b3 = (lane & 8) != 0;
#pragma unroll
    for (int i = 0; i < 8; i++) {
        float t0 = h16[i] + __shfl_xor_sync(FM, h16[i], 8);
        float t1 = h16[8 + i] + __shfl_xor_sync(FM, h16[8 + i], 8);
        h8[i] = b3 ? t1 : t0;
    }
    float h4[4];
    const bool b2 = (lane & 4) != 0;
#pragma unroll
    for (int i = 0; i < 4; i++) {
        float t0 = h8[i] + __shfl_xor_sync(FM, h8[i], 4);
        float t1 = h8[4 + i] + __shfl_xor_sync(FM, h8[4 + i], 4);
        h4[i] = b2 ? t1 : t0;
    }
    float h2[2];
    const bool b1 = (lane & 2) != 0;
#pragma unroll
    for (int i = 0; i < 2; i++) {
        float u0 = h4[i] + __shfl_xor_sync(FM, h4[i], 2);
        float u1 = h4[2 + i] + __shfl_xor_sync(FM, h4[2 + i], 2);
        h2[i] = b1 ? u1 : u0;
    }
    const bool b0 = (lane & 1) != 0;
    float u0 = h2[0] + __shfl_xor_sync(FM, h2[0], 1);
    float u1 = h2[1] + __shfl_xor_sync(FM, h2[1], 1);
    return b0 ? u1 : u0;
}

#define TILE_U4   1024                       // uint4 per 64-col B group
#define GEMM_SMEM_BYTES (3 * TILE_U4 * 16)   // 48 KB -> 2 CTAs/SM

// ===========================================================================
// Single persistent kernel, 288 CTAs x 256 threads (2 CTAs/SM).
// Phase 0 (warp-specialized):
//   warps 0-3: recurrence, rows b = wid*288 + cta (guard b < 1024)
//   warps 4-7: B fragment transform via double-buffered smem stage
// Ticket barrier.  Phase 2: GEMM, CTA tile 128x64, 3-stage cp.async ring.
// ===========================================================================
__global__ void __launch_bounds__(256, 2)
fused_kernel(const float* __restrict__ item,
             const float* __restrict__ user,
             const float* __restrict__ mem_init,
             const int*   __restrict__ user_id,
             const int*   __restrict__ seq,
             const int*   __restrict__ seq_len,
             float* __restrict__ C)
{
    extern __shared__ uint4 smem[];          // 48 KB: phase0 stage / phase2 ring
    const unsigned FM = 0xffffffffu;

    const int tid  = threadIdx.x;
    const int wid  = tid >> 5;
    const int lane = tid & 31;
    const int cta  = blockIdx.x;

    // ======================= PHASE 0 =======================
    if (wid < 4) {
        // ---------------- recurrence: one batch row per warp ----------------
        const int b = wid * NCTAS + cta;
        if (b < B_) {
            float m0[K_], m1[K_];
            const float* mi = mem_init + (size_t)b * K_ * D_;
#pragma unroll
            for (int k = 0; k < K_; k++) {
                m0[k] = mi[k * D_ + lane];
                m1[k] = mi[k * D_ + lane + 32];
            }

            const int T = seq_len[b];
            const int* sq = seq + b * L_;

            for (int t0 = 0; t0 < T; t0 += 8) {
                int nt = min(8, T - t0);
                float e0[8], e1[8];
#pragma unroll
                for (int i = 0; i < 8; i++) {
                    if (i < nt) {
                        int idx = __ldg(sq + t0 + i);
                        e0[i] = __ldg(item + (size_t)idx * D_ + lane);
                        e1[i] = __ldg(item + (size_t)idx * D_ + lane + 32);
                    }
                }
#pragma unroll
                for (int i = 0; i < 8; i++) {
                    if (i >= nt) break;
                    float pad[32];
#pragma unroll
                    for (int k = 0; k < K_; k++)
                        pad[k] = fmaf(m0[k], e0[i], m1[k] * e1[i]);
#pragma unroll
                    for (int k = 20; k < 32; k++) pad[k] = 0.f;
                    float sk = xpose_reduce20(pad, lane);

                    float es = (lane < K_) ? __expf(sk) : 0.f;
                    float sum = es;
#pragma unroll
                    for (int off = 16; off > 0; off >>= 1)
                        sum += __shfl_xor_sync(FM, sum, off);
                    float z_own = es * __fdividef(1.f, sum);

                    float ex0 = __expf(-e0[i]);
                    float ex1 = __expf(-e1[i]);
                    float er0 = __fdividef(1.f, 1.f + ex0);
                    float er1 = __fdividef(1.f, 1.f + ex1);
                    float q0  = ex0 * ex0;
                    float q1  = ex1 * ex1;
                    float ad0 = __fdividef(1.f - q0, 1.f + q0);
                    float ad1 = __fdividef(1.f - q1, 1.f + q1);

#pragma unroll
                    for (int k = 0; k < K_; k++) {
                        float z = __shfl_sync(FM, z_own, k);
                        m0[k] = fmaf(z, fmaf(-m0[k], er0, ad0), m0[k]);
                        m1[k] = fmaf(z, fmaf(-m1[k], er1, ad1), m1[k]);
                    }
                }
            }

            int lidx = __ldg(sq + L_ - 1);
            float l0 = __ldg(item + (size_t)lidx * D_ + lane);
            float l1 = __ldg(item + (size_t)lidx * D_ + lane + 32);
            float pad[32];
#pragma unroll
            for (int k = 0; k < K_; k++)
                pad[k] = fmaf(m0[k], l0, m1[k] * l1);
#pragma unroll
            for (int k = 20; k < 32; k++) pad[k] = 0.f;
            float sk = xpose_reduce20(pad, lane);
            float es = (lane < K_) ? __expf(sk) : 0.f;
            float sum = es;
#pragma unroll
            for (int off = 16; off > 0; off >>= 1)
                sum += __shfl_xor_sync(FM, sum, off);
            float z_own = es * __fdividef(1.f, sum);

            float p0 = 0.f, p1 = 0.f;
#pragma unroll
            for (int k = 0; k < K_; k++) {
                float z = __shfl_sync(FM, z_own, k);
                p0 = fmaf(z, m0[k], p0);
                p1 = fmaf(z, m1[k], p1);
            }
            int uid = __ldg(user_id + b);
            g_pu[b * D_ + lane]      = __ldg(user + (size_t)uid * D_ + lane)      + ALPHA * p0;
            g_pu[b * D_ + lane + 32] = __ldg(user + (size_t)uid * D_ + lane + 32) + ALPHA * p1;
        }
    } else {
        // ------- B fragment transform: team of 4 warps, staged via smem ------
        float* const stage = (float*)smem;           // 2 x 1088 floats
        const uint32_t stage_b = smem_u32(smem);
        const int tid2 = tid - 128;                  // 0..127

        // prologue: stage first group (16 rows x 16 f4, 2 f4 per thread)
        {
            int n0 = cta * 16;
#pragma unroll
            for (int i = 0; i < 2; i++) {
                int idx = tid2 + i * 128;
                int row = idx >> 4, f4 = idx & 15;
                int n = n0 + row;
                unsigned sb = (n < NITEMS) ? 16u : 0u;
                cp_async16z(stage_b + (row * 68 + f4 * 4) * 4,
                            item + (size_t)n * 64 + f4 * 4, sb);
            }
            CP_COMMIT();
        }

        int it = 0;
        for (int gg = cta; gg < NGRP16; gg += NCTAS, it++) {
            const int cur = it & 1;
            {
                int gn = gg + NCTAS;
                if (gn < NGRP16) {
                    int n0 = gn * 16;
#pragma unroll
                    for (int i = 0; i < 2; i++) {
                        int idx = tid2 + i * 128;
                        int row = idx >> 4, f4 = idx & 15;
                        int n = n0 + row;
                        unsigned sb = (n < NITEMS) ? 16u : 0u;
                        cp_async16z(stage_b + ((cur ^ 1) * 1088 + row * 68 + f4 * 4) * 4,
                                    item + (size_t)n * 64 + f4 * 4, sb);
                    }
                }
                CP_COMMIT();
            }
            CP_WAIT(1);
            BARX(1, 128);

            const float* st = stage + cur * 1088;
#pragma unroll
            for (int i = 0; i < 2; i++) {
                int u   = tid2 + i * 128;            // fragment idx in group
                int lu  = u & 31;
                int j   = (u >> 5) & 3;
                int par = u >> 7;
                int w   = lu >> 2;
                int t   = lu & 3;
                int nl  = (w & 1) ? (2 * w - 1 + 2 * par) : (2 * w + 2 * par);
                uint4 v;
                v.x = f2tf32(st[nl * 68 + (j * 4 + 0) * 4 + t]);
                v.y = f2tf32(st[nl * 68 + (j * 4 + 1) * 4 + t]);
                v.z = f2tf32(st[nl * 68 + (j * 4 + 2) * 4 + t]);
                v.w = f2tf32(st[nl * 68 + (j * 4 + 3) * 4 + t]);
                g_bfrag[(size_t)gg * 256 + u] = v;
            }

            BARX(1, 128);
        }
    }

    // ======================= BARRIER =======================
    __threadfence();
    __syncthreads();
    if (tid == 0) {
        unsigned ticket = atomicAdd(&g_bar, 1u);
        unsigned target = (ticket / NCTAS + 1u) * NCTAS;
        while (*(volatile unsigned*)&g_bar < target) { }
    }
    __syncthreads();
    __threadfence();

    // ======================= PHASE 2: GEMM =======================
    // 8 warps: wm = wid>>1 (32-row slice), wn = wid&1 (32-col slice)
    const uint32_t sBb = smem_u32(smem);
    const int wm = wid >> 1;
    const int wn = wid & 1;
    const int g  = lane >> 2;
    const int t2 = lane & 3;

    const int strip = cta & 7;
    const int slot  = cta >> 3;            // 0..35

    uint4 a[2][8];
    {
        const float* pu = g_pu + (size_t)(strip * 128 + wm * 32) * 64;
#pragma unroll
        for (int mi = 0; mi < 2; mi++) {
            int r0 = mi * 16 + g;
#pragma unroll
            for (int ks = 0; ks < 8; ks++) {
                int k0 = ks * 8 + t2;
                a[mi][ks].x = f2tf32(pu[r0 * 64 + k0]);
                a[mi][ks].y = f2tf32(pu[(r0 + 8) * 64 + k0]);
                a[mi][ks].z = f2tf32(pu[r0 * 64 + k0 + 4]);
                a[mi][ks].w = f2tf32(pu[(r0 + 8) * 64 + k0 + 4]);
            }
        }
    }

    const int row_base = strip * 128 + wm * 32;

    // prologue: stage groups for iter 0,1 (4 x cp.async16 per thread)
#pragma unroll
    for (int pf = 0; pf < 2; pf++) {
        int grp = slot + pf * SLOTS;        // max 71 < NGROUPS
        const uint4* src = g_bfrag + (size_t)grp * TILE_U4 + tid;
        uint32_t dst = sBb + (uint32_t)(pf * TILE_U4 + tid) * 16u;
#pragma unroll
        for (int r = 0; r < 4; r++)
            cp_async16(dst + r * 256 * 16, src + r * 256);
        CP_COMMIT();
    }

    int iter = 0;
    for (int grp = slot; grp < NGROUPS; grp += SLOTS, iter++) {
        const int buf = iter - (iter / 3) * 3;
        CP_WAIT(1);
        __syncthreads();

        {
            int nxt = grp + 2 * SLOTS;
            if (nxt < NGROUPS) {
                const int pbuf = (buf + 2 >= 3) ? buf - 1 : buf + 2;
                const uint4* src = g_bfrag + (size_t)nxt * TILE_U4 + tid;
                uint32_t dst = sBb + (uint32_t)(pbuf * TILE_U4 + tid) * 16u;
#pragma unroll
                for (int r = 0; r < 4; r++)
                    cp_async16(dst + r * 256 * 16, src + r * 256);
            }
            CP_COMMIT();
        }

        float acc[2][2][2][4];
#pragma unroll
        for (int i = 0; i < 2; i++)
#pragma unroll
            for (int p = 0; p < 2; p++)
#pragma unroll
                for (int q = 0; q < 2; q++)
#pragma unroll
                    for (int r = 0; r < 4; r++) acc[i][p][q][r] = 0.f;

        const uint4* Bs = smem + buf * TILE_U4;
#pragma unroll
        for (int j = 0; j < 4; j++) {
            uint4 b[2][2];
#pragma unroll
            for (int p = 0; p < 2; p++)
#pragma unroll
                for (int q = 0; q < 2; q++)
                    b[p][q] = Bs[((wn * 4 + p * 2 + q) * 4 + j) * 32 + lane];
#pragma unroll
            for (int s = 0; s < 2; s++) {
                const int ks = 2 * j + s;
#pragma unroll
                for (int mi = 0; mi < 2; mi++)
#pragma unroll
                    for (int p = 0; p < 2; p++)
#pragma unroll
                        for (int q = 0; q < 2; q++) {
                            uint32_t b0 = (s == 0) ? b[p][q].x : b[p][q].z;
                            uint32_t b1 = (s == 0) ? b[p][q].y : b[p][q].w;
                            mma_tf32(acc[mi][p][q][0], acc[mi][p][q][1],
                                     acc[mi][p][q][2], acc[mi][p][q][3],
                                     a[mi][ks].x, a[mi][ks].y, a[mi][ks].z, a[mi][ks].w,
                                     b0, b1);
                        }
            }
        }

        // epilogue: STG.128 streaming store burst
#pragma unroll
        for (int mi = 0; mi < 2; mi++) {
            int row0 = row_base + mi * 16 + g;
#pragma unroll
            for (int p = 0; p < 2; p++) {
                int base16 = grp * 64 + wn * 32 + p * 16;
                if (base16 < NITEMS) {       // NITEMS % 16 == 0
                    int col = base16 + 4 * t2;
                    __stcs((float4*)(C + (size_t)row0 * NITEMS + col),
                           make_float4(acc[mi][p][0][0], acc[mi][p][0][1],
                                       acc[mi][p][1][0], acc[mi][p][1][1]));
                    __stcs((float4*)(C + (size_t)(row0 + 8) * NITEMS + col),
                           make_float4(acc[mi][p][0][2], acc[mi][p][0][3],
                                       acc[mi][p][1][2], acc[mi][p][1][3]));
                }
            }
        }
    }
}

// ===========================================================================
extern "C" void kernel_launch(void* const* d_in, const int* in_sizes, int n_in,
                              void* d_out, int out_size)
{
    const float* item_table  = (const float*)d_in[0];
    const float* user_table  = (const float*)d_in[1];
    const float* memory_init = (const float*)d_in[2];
    const int*   user_id     = (const int*)d_in[3];
    const int*   seq         = (const int*)d_in[4];
    const int*   seq_length  = (const int*)d_in[5];
    float*       scores      = (float*)d_out;

    cudaFuncSetAttribute(fused_kernel,
                         cudaFuncAttributeMaxDynamicSharedMemorySize,
                         GEMM_SMEM_BYTES);

    fused_kernel<<<NCTAS, 256, GEMM_SMEM_BYTES>>>(
        item_table, user_table, memory_init, user_id, seq, seq_length, scores);
}

// round 16
// speedup vs baseline: 1.7158x; 1.0177x over previous
#include <cuda_runtime.h>
#include <cuda_bf16.h>
#include <cstdint>

#define B_      1024
#define L_      50
#define K_      20
#define D_      64
#define NITEMS  100000
#define NUSERS  10000
#define ALPHA   0.2f

#define NT_PAD   12512              // n8-tiles padded to multiple of 16
#define NGROUPS  (NT_PAD / 8)       // 1564 GEMM groups of 64 cols
#define NGRP16   (NT_PAD / 2)       // 6256 transform groups of 16 rows
#define STRIPS   8
#define SLOTS    36
#define NCTAS    (STRIPS * SLOTS)   // 288 CTAs, 2/SM, one wave

__device__ float g_pu[B_ * D_];
// B fragments: [nt][j(4)][lane(32)] uint4 (k-steps 2j,2j+1), column-paired
__device__ uint4 g_bfrag[NT_PAD * 4 * 32];     // 25.6 MB
__device__ unsigned g_bar = 0;                 // monotonic ticket barrier

__device__ __forceinline__ uint32_t f2tf32(float x) {
    uint32_t u;
    asm("cvt.rn.tf32.f32 %0, %1;" : "=r"(u) : "f"(x));
    return u;
}
__device__ __forceinline__ uint32_t smem_u32(const void* p) {
    uint32_t a;
    asm("{ .reg .u64 t; cvta.to.shared.u64 t, %1; cvt.u32.u64 %0, t; }"
        : "=r"(a) : "l"(p));
    return a;
}
__device__ __forceinline__ void cp_async16(uint32_t dst, const void* src) {
    asm volatile("cp.async.cg.shared.global [%0], [%1], 16;"
                 :: "r"(dst), "l"(src) : "memory");
}
__device__ __forceinline__ void cp_async16z(uint32_t dst, const void* src,
                                            unsigned sbytes) {
    asm volatile("cp.async.cg.shared.global [%0], [%1], 16, %2;"
                 :: "r"(dst), "l"(src), "r"(sbytes) : "memory");
}
#define CP_COMMIT() asm volatile("cp.async.commit_group;" ::: "memory")
#define CP_WAIT(n)  asm volatile("cp.async.wait_group %0;" :: "n"(n) : "memory")
#define BARX(id, n) asm volatile("bar.sync %0, %1;" :: "r"(id), "r"(n) : "memory")

__device__ __forceinline__ void mma_tf32(float& c0, float& c1, float& c2, float& c3,
                                         uint32_t a0, uint32_t a1, uint32_t a2, uint32_t a3,
                                         uint32_t b0, uint32_t b1) {
    asm volatile("mma.sync.aligned.m16n8k8.row.col.f32.tf32.tf32.f32 "
                 "{%0,%1,%2,%3}, {%4,%5,%6,%7}, {%8,%9}, {%0,%1,%2,%3};"
                 : "+f"(c0), "+f"(c1), "+f"(c2), "+f"(c3)
                 : "r"(a0), "r"(a1), "r"(a2), "r"(a3), "r"(b0), "r"(b1));
}

// ---------------------------------------------------------------------------
// Multi-value reduce-and-transpose: lane l ends with sum over lanes of v[l]
// for l<20.  50 SHFLs, depth 5.
// ---------------------------------------------------------------------------
__device__ __forceinline__ float xpose_reduce20(const float* v, int lane) {
    const unsigned FM = 0xffffffffu;
    float h16[16];
    const bool b4 = (lane & 16) != 0;
#pragma unroll
    for (int i = 0; i < 16; i++) {
        float t0 = v[i] + __shfl_xor_sync(FM, v[i], 16);
        float t1 = (i < 4) ? (v[16 + i] + __shfl_xor_sync(FM, v[16 + i], 16)) : 0.f;
        h16[i] = b4 ? t1 : t0;
    }
    float h8[8];
    const bool b3 = (lane & 8) != 0;
#pragma unroll
    for (int i = 0; i < 8; i++) {
        float t0 = h16[i] + __shfl_xor_sync(FM, h16[i], 8);
        float t1 = h16[8 + i] + __shfl_xor_sync(FM, h16[8 + i], 8);
        h8[i] = b3 ? t1 : t0;
    }
    float h4[4];
    const bool b2 = (lane & 4) != 0;
#pragma unroll
    for (int i = 0; i < 4; i++) {
        float t0 = h8[i] + __shfl_xor_sync(FM, h8[i], 4);
        float t1 = h8[4 + i] + __shfl_xor_sync(FM, h8[4 + i], 4);
        h4[i] = b2 ? t1 : t0;
    }
    float h2[2];
    const bool b1 = (lane & 2) != 0;
#pragma unroll
    for (int i = 0; i < 2; i++) {
        float u0 = h4[i] + __shfl_xor_sync(FM, h4[i], 2);
        float u1 = h4[2 + i] + __shfl_xor_sync(FM, h4[2 + i], 2);
        h2[i] = b1 ? u1 : u0;
    }
    const bool b0 = (lane & 1) != 0;
    float u0 = h2[0] + __shfl_xor_sync(FM, h2[0], 1);
    float u1 = h2[1] + __shfl_xor_sync(FM, h2[1], 1);
    return b0 ? u1 : u0;
}

#define TILE_U4   1024                       // uint4 per 64-col B group
#define NBUF      4
#define GEMM_SMEM_BYTES (NBUF * TILE_U4 * 16)   // 64 KB -> 2 CTAs/SM (128KB<=228)

// ===========================================================================
// Single persistent kernel, 288 CTAs x 256 threads (2 CTAs/SM).
// Phase 0 (warp-specialized):
//   warps 0-3: recurrence, rows b = wid*288 + cta
//   warps 4-7: B fragment transform via double-buffered smem stage
// Ticket barrier.  Phase 2: GEMM, CTA tile 128x64, 4-stage cp.async ring
// (prefetch distance 3, CP_WAIT(2)).
// ===========================================================================
__global__ void __launch_bounds__(256, 2)
fused_kernel(const float* __restrict__ item,
             const float* __restrict__ user,
             const float* __restrict__ mem_init,
             const int*   __restrict__ user_id,
             const int*   __restrict__ seq,
             const int*   __restrict__ seq_len,
             float* __restrict__ C)
{
    extern __shared__ uint4 smem[];          // 64 KB: phase0 stage / phase2 ring
    const unsigned FM = 0xffffffffu;

    const int tid  = threadIdx.x;
    const int wid  = tid >> 5;
    const int lane = tid & 31;
    const int cta  = blockIdx.x;

    // ======================= PHASE 0 =======================
    if (wid < 4) {
        // ---------------- recurrence: one batch row per warp ----------------
        const int b = wid * NCTAS + cta;
        if (b < B_) {
            float m0[K_], m1[K_];
            const float* mi = mem_init + (size_t)b * K_ * D_;
#pragma unroll
            for (int k = 0; k < K_; k++) {
                m0[k] = mi[k * D_ + lane];
                m1[k] = mi[k * D_ + lane + 32];
            }

            const int T = seq_len[b];
            const int* sq = seq + b * L_;

            for (int t0 = 0; t0 < T; t0 += 8) {
                int nt = min(8, T - t0);
                float e0[8], e1[8];
#pragma unroll
                for (int i = 0; i < 8; i++) {
                    if (i < nt) {
                        int idx = __ldg(sq + t0 + i);
                        e0[i] = __ldg(item + (size_t)idx * D_ + lane);
                        e1[i] = __ldg(item + (size_t)idx * D_ + lane + 32);
                    }
                }
#pragma unroll
                for (int i = 0; i < 8; i++) {
                    if (i >= nt) break;
                    // gates first (independent of the reduce chain; MUFU work
                    // hides under the shuffle latency)
                    float ex0 = __expf(-e0[i]);
                    float ex1 = __expf(-e1[i]);
                    float er0 = __fdividef(1.f, 1.f + ex0);
                    float er1 = __fdividef(1.f, 1.f + ex1);
                    float q0  = ex0 * ex0;
                    float q1  = ex1 * ex1;
                    float ad0 = __fdividef(1.f - q0, 1.f + q0);
                    float ad1 = __fdividef(1.f - q1, 1.f + q1);

                    float pad[32];
#pragma unroll
                    for (int k = 0; k < K_; k++)
                        pad[k] = fmaf(m0[k], e0[i], m1[k] * e1[i]);
#pragma unroll
                    for (int k = 20; k < 32; k++) pad[k] = 0.f;

                    // w[k] = ad - m[k]*er, independent of z: overlaps reduce
                    float w0[K_], w1[K_];
#pragma unroll
                    for (int k = 0; k < K_; k++) {
                        w0[k] = fmaf(-m0[k], er0, ad0);
                        w1[k] = fmaf(-m1[k], er1, ad1);
                    }

                    float sk = xpose_reduce20(pad, lane);
                    float es = (lane < K_) ? __expf(sk) : 0.f;
                    float sum = es;
#pragma unroll
                    for (int off = 16; off > 0; off >>= 1)
                        sum += __shfl_xor_sync(FM, sum, off);
                    float z_own = es * __fdividef(1.f, sum);

#pragma unroll
                    for (int k = 0; k < K_; k++) {
                        float z = __shfl_sync(FM, z_own, k);
                        m0[k] = fmaf(z, w0[k], m0[k]);
                        m1[k] = fmaf(z, w1[k], m1[k]);
                    }
                }
            }

            int lidx = __ldg(sq + L_ - 1);
            float l0 = __ldg(item + (size_t)lidx * D_ + lane);
            float l1 = __ldg(item + (size_t)lidx * D_ + lane + 32);
            float pad[32];
#pragma unroll
            for (int k = 0; k < K_; k++)
                pad[k] = fmaf(m0[k], l0, m1[k] * l1);
#pragma unroll
            for (int k = 20; k < 32; k++) pad[k] = 0.f;
            float sk = xpose_reduce20(pad, lane);
            float es = (lane < K_) ? __expf(sk) : 0.f;
            float sum = es;
#pragma unroll
            for (int off = 16; off > 0; off >>= 1)
                sum += __shfl_xor_sync(FM, sum, off);
            float z_own = es * __fdividef(1.f, sum);

            float p0 = 0.f, p1 = 0.f;
#pragma unroll
            for (int k = 0; k < K_; k++) {
                float z = __shfl_sync(FM, z_own, k);
                p0 = fmaf(z, m0[k], p0);
                p1 = fmaf(z, m1[k], p1);
            }
            int uid = __ldg(user_id + b);
            g_pu[b * D_ + lane]      = __ldg(user + (size_t)uid * D_ + lane)      + ALPHA * p0;
            g_pu[b * D_ + lane + 32] = __ldg(user + (size_t)uid * D_ + lane + 32) + ALPHA * p1;
        }
    } else {
        // ------- B fragment transform: team of 4 warps, staged via smem ------
        float* const stage = (float*)smem;           // 2 x 1088 floats
        const uint32_t stage_b = smem_u32(smem);
        const int tid2 = tid - 128;                  // 0..127

        {
            int n0 = cta * 16;
#pragma unroll
            for (int i = 0; i < 2; i++) {
                int idx = tid2 + i * 128;
                int row = idx >> 4, f4 = idx & 15;
                int n = n0 + row;
                unsigned sb = (n < NITEMS) ? 16u : 0u;
                cp_async16z(stage_b + (row * 68 + f4 * 4) * 4,
                            item + (size_t)n * 64 + f4 * 4, sb);
            }
            CP_COMMIT();
        }

        int it = 0;
        for (int gg = cta; gg < NGRP16; gg += NCTAS, it++) {
            const int cur = it & 1;
            {
                int gn = gg + NCTAS;
                if (gn < NGRP16) {
                    int n0 = gn * 16;
#pragma unroll
                    for (int i = 0; i < 2; i++) {
                        int idx = tid2 + i * 128;
                        int row = idx >> 4, f4 = idx & 15;
                        int n = n0 + row;
                        unsigned sb = (n < NITEMS) ? 16u : 0u;
                        cp_async16z(stage_b + ((cur ^ 1) * 1088 + row * 68 + f4 * 4) * 4,
                                    item + (size_t)n * 64 + f4 * 4, sb);
                    }
                }
                CP_COMMIT();
            }
            CP_WAIT(1);
            BARX(1, 128);

            const float* st = stage + cur * 1088;
#pragma unroll
            for (int i = 0; i < 2; i++) {
                int u   = tid2 + i * 128;
                int lu  = u & 31;
                int j   = (u >> 5) & 3;
                int par = u >> 7;
                int w   = lu >> 2;
                int t   = lu & 3;
                int nl  = (w & 1) ? (2 * w - 1 + 2 * par) : (2 * w + 2 * par);
                uint4 v;
                v.x = f2tf32(st[nl * 68 + (j * 4 + 0) * 4 + t]);
                v.y = f2tf32(st[nl * 68 + (j * 4 + 1) * 4 + t]);
                v.z = f2tf32(st[nl * 68 + (j * 4 + 2) * 4 + t]);
                v.w = f2tf32(st[nl * 68 + (j * 4 + 3) * 4 + t]);
                g_bfrag[(size_t)gg * 256 + u] = v;
            }

            BARX(1, 128);
        }
    }

    // ======================= BARRIER =======================
    __threadfence();
    __syncthreads();
    if (tid == 0) {
        unsigned ticket = atomicAdd(&g_bar, 1u);
        unsigned target = (ticket / NCTAS + 1u) * NCTAS;
        while (*(volatile unsigned*)&g_bar < target) { }
    }
    __syncthreads();
    __threadfence();

    // ======================= PHASE 2: GEMM =======================
    const uint32_t sBb = smem_u32(smem);
    const int wm = wid >> 1;
    const int wn = wid & 1;
    const int g  = lane >> 2;
    const int t2 = lane & 3;

    const int strip = cta & 7;
    const int slot  = cta >> 3;            // 0..35

    uint4 a[2][8];
    {
        const float* pu = g_pu + (size_t)(strip * 128 + wm * 32) * 64;
#pragma unroll
        for (int mi = 0; mi < 2; mi++) {
            int r0 = mi * 16 + g;
#pragma unroll
            for (int ks = 0; ks < 8; ks++) {
                int k0 = ks * 8 + t2;
                a[mi][ks].x = f2tf32(pu[r0 * 64 + k0]);
                a[mi][ks].y = f2tf32(pu[(r0 + 8) * 64 + k0]);
                a[mi][ks].z = f2tf32(pu[r0 * 64 + k0 + 4]);
                a[mi][ks].w = f2tf32(pu[(r0 + 8) * 64 + k0 + 4]);
            }
        }
    }

    const int row_base = strip * 128 + wm * 32;

    // prologue: stage groups for iter 0,1,2 into buffers 0,1,2
#pragma unroll
    for (int pf = 0; pf < 3; pf++) {
        int grp = slot + pf * SLOTS;        // max 107 < NGROUPS
        const uint4* src = g_bfrag + (size_t)grp * TILE_U4 + tid;
        uint32_t dst = sBb + (uint32_t)(pf * TILE_U4 + tid) * 16u;
#pragma unroll
        for (int r = 0; r < 4; r++)
            cp_async16(dst + r * 256 * 16, src + r * 256);
        CP_COMMIT();
    }

    int iter = 0;
    for (int grp = slot; grp < NGROUPS; grp += SLOTS, iter++) {
        const int buf = iter & 3;
        CP_WAIT(2);
        __syncthreads();

        // prefetch iter+3 into buffer (iter+3)&3 (freed at this sync)
        {
            int nxt = grp + 3 * SLOTS;
            if (nxt < NGROUPS) {
                const int pbuf = (iter + 3) & 3;
                const uint4* src = g_bfrag + (size_t)nxt * TILE_U4 + tid;
                uint32_t dst = sBb + (uint32_t)(pbuf * TILE_U4 + tid) * 16u;
#pragma unroll
                for (int r = 0; r < 4; r++)
                    cp_async16(dst + r * 256 * 16, src + r * 256);
            }
            CP_COMMIT();
        }

        float acc[2][2][2][4];
#pragma unroll
        for (int i = 0; i < 2; i++)
#pragma unroll
            for (int p = 0; p < 2; p++)
#pragma unroll
                for (int q = 0; q < 2; q++)
#pragma unroll
                    for (int r = 0; r < 4; r++) acc[i][p][q][r] = 0.f;

        const uint4* Bs = smem + buf * TILE_U4;
#pragma unroll
        for (int j = 0; j < 4; j++) {
            uint4 b[2][2];
#pragma unroll
            for (int p = 0; p < 2; p++)
#pragma unroll
                for (int q = 0; q < 2; q++)
                    b[p][q] = Bs[((wn * 4 + p * 2 + q) * 4 + j) * 32 + lane];
#pragma unroll
            for (int s = 0; s < 2; s++) {
                const int ks = 2 * j + s;
#pragma unroll
                for (int mi = 0; mi < 2; mi++)
#pragma unroll
                    for (int p = 0; p < 2; p++)
#pragma unroll
                        for (int q = 0; q < 2; q++) {
                            uint32_t b0 = (s == 0) ? b[p][q].x : b[p][q].z;
                            uint32_t b1 = (s == 0) ? b[p][q].y : b[p][q].w;
                            mma_tf32(acc[mi][p][q][0], acc[mi][p][q][1],
                                     acc[mi][p][q][2], acc[mi][p][q][3],
                                     a[mi][ks].x, a[mi][ks].y, a[mi][ks].z, a[mi][ks].w,
                                     b0, b1);
                        }
            }
        }

        // epilogue: STG.128 streaming store burst
#pragma unroll
        for (int mi = 0; mi < 2; mi++) {
            int row0 = row_base + mi * 16 + g;
#pragma unroll
            for (int p = 0; p < 2; p++) {
                int base16 = grp * 64 + wn * 32 + p * 16;
                if (base16 < NITEMS) {       // NITEMS % 16 == 0
                    int col = base16 + 4 * t2;
                    __stcs((float4*)(C + (size_t)row0 * NITEMS + col),
                           make_float4(acc[mi][p][0][0], acc[mi][p][0][1],
                                       acc[mi][p][1][0], acc[mi][p][1][1]));
                    __stcs((float4*)(C + (size_t)(row0 + 8) * NITEMS + col),
                           make_float4(acc[mi][p][0][2], acc[mi][p][0][3],
                                       acc[mi][p][1][2], acc[mi][p][1][3]));
                }
            }
        }
    }
}

// ===========================================================================
extern "C" void kernel_launch(void* const* d_in, const int* in_sizes, int n_in,
                              void* d_out, int out_size)
{
    const float* item_table  = (const float*)d_in[0];
    const float* user_table  = (const float*)d_in[1];
    const float* memory_init = (const float*)d_in[2];
    const int*   user_id     = (const int*)d_in[3];
    const int*   seq         = (const int*)d_in[4];
    const int*   seq_length  = (const int*)d_in[5];
    float*       scores      = (float*)d_out;

    cudaFuncSetAttribute(fused_kernel,
                         cudaFuncAttributeMaxDynamicSharedMemorySize,
                         GEMM_SMEM_BYTES);

    fused_kernel<<<NCTAS, 256, GEMM_SMEM_BYTES>>>(
        item_table, user_table, memory_init, user_id, seq, seq_length, scores);
}

// round 17
// speedup vs baseline: 1.7384x; 1.0131x over previous
#include <cuda_runtime.h>
#include <cuda_bf16.h>
#include <cstdint>

#define B_      1024
#define L_      50
#define K_      20
#define D_      64
#define NITEMS  100000
#define NUSERS  10000
#define ALPHA   0.2f

#define NT_PAD   12512              // n8-tiles padded to multiple of 16
#define NGROUPS  (NT_PAD / 8)       // 1564 GEMM groups of 64 cols
#define NGRP16   (NT_PAD / 2)       // 6256 transform groups of 16 rows
#define STRIPS   8
#define SLOTS    36
#define NCTAS    (STRIPS * SLOTS)   // 288 CTAs, 2/SM, one wave

__device__ float g_pu[B_ * D_];
// B fragments: [nt][j(4)][lane(32)] uint4 (k-steps 2j,2j+1), column-paired
__device__ uint4 g_bfrag[NT_PAD * 4 * 32];     // 25.6 MB
__device__ unsigned g_bar = 0;                 // monotonic ticket barrier

__device__ __forceinline__ uint32_t f2tf32(float x) {
    uint32_t u;
    asm("cvt.rn.tf32.f32 %0, %1;" : "=r"(u) : "f"(x));
    return u;
}
__device__ __forceinline__ uint32_t smem_u32(const void* p) {
    uint32_t a;
    asm("{ .reg .u64 t; cvta.to.shared.u64 t, %1; cvt.u32.u64 %0, t; }"
        : "=r"(a) : "l"(p));
    return a;
}
__device__ __forceinline__ void cp_async16(uint32_t dst, const void* src) {
    asm volatile("cp.async.cg.shared.global [%0], [%1], 16;"
                 :: "r"(dst), "l"(src) : "memory");
}
__device__ __forceinline__ void cp_async16z(uint32_t dst, const void* src,
                                            unsigned sbytes) {
    asm volatile("cp.async.cg.shared.global [%0], [%1], 16, %2;"
                 :: "r"(dst), "l"(src), "r"(sbytes) : "memory");
}
#define CP_COMMIT() asm volatile("cp.async.commit_group;" ::: "memory")
#define CP_WAIT(n)  asm volatile("cp.async.wait_group %0;" :: "n"(n) : "memory")
#define BARX(id, n) asm volatile("bar.sync %0, %1;" :: "r"(id), "r"(n) : "memory")

__device__ __forceinline__ void mma_tf32(float& c0, float& c1, float& c2, float& c3,
                                         uint32_t a0, uint32_t a1, uint32_t a2, uint32_t a3,
                                         uint32_t b0, uint32_t b1) {
    asm volatile("mma.sync.aligned.m16n8k8.row.col.f32.tf32.tf32.f32 "
                 "{%0,%1,%2,%3}, {%4,%5,%6,%7}, {%8,%9}, {%0,%1,%2,%3};"
                 : "+f"(c0), "+f"(c1), "+f"(c2), "+f"(c3)
                 : "r"(a0), "r"(a1), "r"(a2), "r"(a3), "r"(b0), "r"(b1));
}

// ---------------------------------------------------------------------------
// Multi-value reduce-and-transpose: lane l ends with sum over lanes of v[l]
// for l<20.  50 SHFLs, depth 5.
// ---------------------------------------------------------------------------
__device__ __forceinline__ float xpose_reduce20(const float* v, int lane) {
    const unsigned FM = 0xffffffffu;
    float h16[16];
    const bool b4 = (lane & 16) != 0;
#pragma unroll
    for (int i = 0; i < 16; i++) {
        float t0 = v[i] + __shfl_xor_sync(FM, v[i], 16);
        float t1 = (i < 4) ? (v[16 + i] + __shfl_xor_sync(FM, v[16 + i], 16)) : 0.f;
        h16[i] = b4 ? t1 : t0;
    }
    float h8[8];
    const bool b3 = (lane & 8) != 0;
#pragma unroll
    for (int i = 0; i < 8; i++) {
        float t0 = h16[i] + __shfl_xor_sync(FM, h16[i], 8);
        float t1 = h16[8 + i] + __shfl_xor_sync(FM, h16[8 + i], 8);
        h8[i] = b3 ? t1 : t0;
    }
    float h4[4];
    const bool b2 = (lane & 4) != 0;
#pragma unroll
    for (int i = 0; i < 4; i++) {
        float t0 = h8[i] + __shfl_xor_sync(FM, h8[i], 4);
        float t1 = h8[4 + i] + __shfl_xor_sync(FM, h8[4 + i], 4);
        h4[i] = b2 ? t1 : t0;
    }
    float h2[2];
    const bool b1 = (lane & 2) != 0;
#pragma unroll
    for (int i = 0; i < 2; i++) {
        float u0 = h4[i] + __shfl_xor_sync(FM, h4[i], 2);
        float u1 = h4[2 + i] + __shfl_xor_sync(FM, h4[2 + i], 2);
        h2[i] = b1 ? u1 : u0;
    }
    const bool b0 = (lane & 1) != 0;
    float u0 = h2[0] + __shfl_xor_sync(FM, h2[0], 1);
    float u1 = h2[1] + __shfl_xor_sync(FM, h2[1], 1);
    return b0 ? u1 : u0;
}

#define TILE_U4   1024                       // uint4 per 64-col B group
#define NBUF      4                          // two pairs
#define GEMM_SMEM_BYTES (NBUF * TILE_U4 * 16)   // 64 KB -> 2 CTAs/SM

// ===========================================================================
// Single persistent kernel, 288 CTAs x 256 threads (2 CTAs/SM).
// Phase 0 (warp-specialized):
//   warps 0-3: recurrence, rows b = wid*288 + cta
//   warps 4-7: B fragment transform via double-buffered smem stage
// Ticket barrier.
// Phase 2: GEMM, CTA tile 128x64, PAIR-granular double buffering:
// two tiles per CP_WAIT(0) + __syncthreads (half the sync frequency).
// ===========================================================================
__global__ void __launch_bounds__(256, 2)
fused_kernel(const float* __restrict__ item,
             const float* __restrict__ user,
             const float* __restrict__ mem_init,
             const int*   __restrict__ user_id,
             const int*   __restrict__ seq,
             const int*   __restrict__ seq_len,
             float* __restrict__ C)
{
    extern __shared__ uint4 smem[];          // 64 KB: phase0 stage / phase2 ring
    const unsigned FM = 0xffffffffu;

    const int tid  = threadIdx.x;
    const int wid  = tid >> 5;
    const int lane = tid & 31;
    const int cta  = blockIdx.x;

    // ======================= PHASE 0 =======================
    if (wid < 4) {
        // ---------------- recurrence: one batch row per warp ----------------
        const int b = wid * NCTAS + cta;
        if (b < B_) {
            float m0[K_], m1[K_];
            const float* mi = mem_init + (size_t)b * K_ * D_;
#pragma unroll
            for (int k = 0; k < K_; k++) {
                m0[k] = mi[k * D_ + lane];
                m1[k] = mi[k * D_ + lane + 32];
            }

            const int T = seq_len[b];
            const int* sq = seq + b * L_;

            for (int t0 = 0; t0 < T; t0 += 8) {
                int nt = min(8, T - t0);
                float e0[8], e1[8];
#pragma unroll
                for (int i = 0; i < 8; i++) {
                    if (i < nt) {
                        int idx = __ldg(sq + t0 + i);
                        e0[i] = __ldg(item + (size_t)idx * D_ + lane);
                        e1[i] = __ldg(item + (size_t)idx * D_ + lane + 32);
                    }
                }
#pragma unroll
                for (int i = 0; i < 8; i++) {
                    if (i >= nt) break;
                    float ex0 = __expf(-e0[i]);
                    float ex1 = __expf(-e1[i]);
                    float er0 = __fdividef(1.f, 1.f + ex0);
                    float er1 = __fdividef(1.f, 1.f + ex1);
                    float q0  = ex0 * ex0;
                    float q1  = ex1 * ex1;
                    float ad0 = __fdividef(1.f - q0, 1.f + q0);
                    float ad1 = __fdividef(1.f - q1, 1.f + q1);

                    float pad[32];
#pragma unroll
                    for (int k = 0; k < K_; k++)
                        pad[k] = fmaf(m0[k], e0[i], m1[k] * e1[i]);
#pragma unroll
                    for (int k = 20; k < 32; k++) pad[k] = 0.f;

                    float w0[K_], w1[K_];
#pragma unroll
                    for (int k = 0; k < K_; k++) {
                        w0[k] = fmaf(-m0[k], er0, ad0);
                        w1[k] = fmaf(-m1[k], er1, ad1);
                    }

                    float sk = xpose_reduce20(pad, lane);
                    float es = (lane < K_) ? __expf(sk) : 0.f;
                    float sum = es;
#pragma unroll
                    for (int off = 16; off > 0; off >>= 1)
                        sum += __shfl_xor_sync(FM, sum, off);
                    float z_own = es * __fdividef(1.f, sum);

#pragma unroll
                    for (int k = 0; k < K_; k++) {
                        float z = __shfl_sync(FM, z_own, k);
                        m0[k] = fmaf(z, w0[k], m0[k]);
                        m1[k] = fmaf(z, w1[k], m1[k]);
                    }
                }
            }

            int lidx = __ldg(sq + L_ - 1);
            float l0 = __ldg(item + (size_t)lidx * D_ + lane);
            float l1 = __ldg(item + (size_t)lidx * D_ + lane + 32);
            float pad[32];
#pragma unroll
            for (int k = 0; k < K_; k++)
                pad[k] = fmaf(m0[k], l0, m1[k] * l1);
#pragma unroll
            for (int k = 20; k < 32; k++) pad[k] = 0.f;
            float sk = xpose_reduce20(pad, lane);
            float es = (lane < K_) ? __expf(sk) : 0.f;
            float sum = es;
#pragma unroll
            for (int off = 16; off > 0; off >>= 1)
                sum += __shfl_xor_sync(FM, sum, off);
            float z_own = es * __fdividef(1.f, sum);

            float p0 = 0.f, p1 = 0.f;
#pragma unroll
            for (int k = 0; k < K_; k++) {
                float z = __shfl_sync(FM, z_own, k);
                p0 = fmaf(z, m0[k], p0);
                p1 = fmaf(z, m1[k], p1);
            }
            int uid = __ldg(user_id + b);
            g_pu[b * D_ + lane]      = __ldg(user + (size_t)uid * D_ + lane)      + ALPHA * p0;
            g_pu[b * D_ + lane + 32] = __ldg(user + (size_t)uid * D_ + lane + 32) + ALPHA * p1;
        }
    } else {
        // ------- B fragment transform: team of 4 warps, staged via smem ------
        float* const stage = (float*)smem;           // 2 x 1088 floats
        const uint32_t stage_b = smem_u32(smem);
        const int tid2 = tid - 128;                  // 0..127

        {
            int n0 = cta * 16;
#pragma unroll
            for (int i = 0; i < 2; i++) {
                int idx = tid2 + i * 128;
                int row = idx >> 4, f4 = idx & 15;
                int n = n0 + row;
                unsigned sb = (n < NITEMS) ? 16u : 0u;
                cp_async16z(stage_b + (row * 68 + f4 * 4) * 4,
                            item + (size_t)n * 64 + f4 * 4, sb);
            }
            CP_COMMIT();
        }

        int it = 0;
        for (int gg = cta; gg < NGRP16; gg += NCTAS, it++) {
            const int cur = it & 1;
            {
                int gn = gg + NCTAS;
                if (gn < NGRP16) {
                    int n0 = gn * 16;
#pragma unroll
                    for (int i = 0; i < 2; i++) {
                        int idx = tid2 + i * 128;
                        int row = idx >> 4, f4 = idx & 15;
                        int n = n0 + row;
                        unsigned sb = (n < NITEMS) ? 16u : 0u;
                        cp_async16z(stage_b + ((cur ^ 1) * 1088 + row * 68 + f4 * 4) * 4,
                                    item + (size_t)n * 64 + f4 * 4, sb);
                    }
                }
                CP_COMMIT();
            }
            CP_WAIT(1);
            BARX(1, 128);

            const float* st = stage + cur * 1088;
#pragma unroll
            for (int i = 0; i < 2; i++) {
                int u   = tid2 + i * 128;
                int lu  = u & 31;
                int j   = (u >> 5) & 3;
                int par = u >> 7;
                int w   = lu >> 2;
                int t   = lu & 3;
                int nl  = (w & 1) ? (2 * w - 1 + 2 * par) : (2 * w + 2 * par);
                uint4 v;
                v.x = f2tf32(st[nl * 68 + (j * 4 + 0) * 4 + t]);
                v.y = f2tf32(st[nl * 68 + (j * 4 + 1) * 4 + t]);
                v.z = f2tf32(st[nl * 68 + (j * 4 + 2) * 4 + t]);
                v.w = f2tf32(st[nl * 68 + (j * 4 + 3) * 4 + t]);
                g_bfrag[(size_t)gg * 256 + u] = v;
            }

            BARX(1, 128);
        }
    }

    // ======================= BARRIER =======================
    __threadfence();
    __syncthreads();
    if (tid == 0) {
        unsigned ticket = atomicAdd(&g_bar, 1u);
        unsigned target = (ticket / NCTAS + 1u) * NCTAS;
        while (*(volatile unsigned*)&g_bar < target) { }
    }
    __syncthreads();
    __threadfence();

    // ======================= PHASE 2: GEMM =======================
    const uint32_t sBb = smem_u32(smem);
    const int wm = wid >> 1;
    const int wn = wid & 1;
    const int g  = lane >> 2;
    const int t2 = lane & 3;

    const int strip = cta & 7;
    const int slot  = cta >> 3;            // 0..35

    uint4 a[2][8];
    {
        const float* pu = g_pu + (size_t)(strip * 128 + wm * 32) * 64;
#pragma unroll
        for (int mi = 0; mi < 2; mi++) {
            int r0 = mi * 16 + g;
#pragma unroll
            for (int ks = 0; ks < 8; ks++) {
                int k0 = ks * 8 + t2;
                a[mi][ks].x = f2tf32(pu[r0 * 64 + k0]);
                a[mi][ks].y = f2tf32(pu[(r0 + 8) * 64 + k0]);
                a[mi][ks].z = f2tf32(pu[r0 * 64 + k0 + 4]);
                a[mi][ks].w = f2tf32(pu[(r0 + 8) * 64 + k0 + 4]);
            }
        }
    }

    const int row_base = strip * 128 + wm * 32;

    // ---- helpers as lambdas ----
    auto issue_pair = [&](int gbase, int pair_off /* uint4 offset */) {
#pragma unroll
        for (int tI = 0; tI < 2; tI++) {
            int grp = gbase + tI * SLOTS;
            if (grp < NGROUPS) {
                const uint4* src = g_bfrag + (size_t)grp * TILE_U4 + tid;
                uint32_t dst = sBb + (uint32_t)(pair_off + tI * TILE_U4 + tid) * 16u;
#pragma unroll
                for (int r = 0; r < 4; r++)
                    cp_async16(dst + r * 256 * 16, src + r * 256);
            }
        }
        CP_COMMIT();
    };

    auto compute_store = [&](const uint4* Bs, int grp) {
        float acc[2][2][2][4];
#pragma unroll
        for (int i = 0; i < 2; i++)
#pragma unroll
            for (int p = 0; p < 2; p++)
#pragma unroll
                for (int q = 0; q < 2; q++)
#pragma unroll
                    for (int r = 0; r < 4; r++) acc[i][p][q][r] = 0.f;

#pragma unroll
        for (int j = 0; j < 4; j++) {
            uint4 b[2][2];
#pragma unroll
            for (int p = 0; p < 2; p++)
#pragma unroll
                for (int q = 0; q < 2; q++)
                    b[p][q] = Bs[((wn * 4 + p * 2 + q) * 4 + j) * 32 + lane];
#pragma unroll
            for (int s = 0; s < 2; s++) {
                const int ks = 2 * j + s;
#pragma unroll
                for (int mi = 0; mi < 2; mi++)
#pragma unroll
                    for (int p = 0; p < 2; p++)
#pragma unroll
                        for (int q = 0; q < 2; q++) {
                            uint32_t b0 = (s == 0) ? b[p][q].x : b[p][q].z;
                            uint32_t b1 = (s == 0) ? b[p][q].y : b[p][q].w;
                            mma_tf32(acc[mi][p][q][0], acc[mi][p][q][1],
                                     acc[mi][p][q][2], acc[mi][p][q][3],
                                     a[mi][ks].x, a[mi][ks].y, a[mi][ks].z, a[mi][ks].w,
                                     b0, b1);
                        }
            }
        }

#pragma unroll
        for (int mi = 0; mi < 2; mi++) {
            int row0 = row_base + mi * 16 + g;
#pragma unroll
            for (int p = 0; p < 2; p++) {
                int base16 = grp * 64 + wn * 32 + p * 16;
                if (base16 < NITEMS) {       // NITEMS % 16 == 0
                    int col = base16 + 4 * t2;
                    __stcs((float4*)(C + (size_t)row0 * NITEMS + col),
                           make_float4(acc[mi][p][0][0], acc[mi][p][0][1],
                                       acc[mi][p][1][0], acc[mi][p][1][1]));
                    __stcs((float4*)(C + (size_t)(row0 + 8) * NITEMS + col),
                           make_float4(acc[mi][p][0][2], acc[mi][p][0][3],
                                       acc[mi][p][1][2], acc[mi][p][1][3]));
                }
            }
        }
    };

    // prologue: pair 0 (groups slot, slot+SLOTS) into bufs 0,1
    issue_pair(slot, 0);

    int jp = 0;
    for (int grp0 = slot; grp0 < NGROUPS; grp0 += 2 * SLOTS, jp++) {
        const int cur_off = (jp & 1) * 2 * TILE_U4;
        const int nxt_off = ((jp + 1) & 1) * 2 * TILE_U4;

        CP_WAIT(0);              // this pair's copies complete
        __syncthreads();         // all warps done with previous pair's buffers

        // prefetch next pair into the other buffers (~1 super-iter in flight)
        int nbase = grp0 + 2 * SLOTS;
        if (nbase < NGROUPS)
            issue_pair(nbase, nxt_off);
        else
            CP_COMMIT();         // keep group count consistent (empty group)

        compute_store(smem + cur_off, grp0);
        int grp1 = grp0 + SLOTS;
        if (grp1 < NGROUPS)
            compute_store(smem + cur_off + TILE_U4, grp1);
    }
}

// ===========================================================================
extern "C" void kernel_launch(void* const* d_in, const int* in_sizes, int n_in,
                              void* d_out, int out_size)
{
    const float* item_table  = (const float*)d_in[0];
    const float* user_table  = (const float*)d_in[1];
    const float* memory_init = (const float*)d_in[2];
    const int*   user_id     = (const int*)d_in[3];
    const int*   seq         = (const int*)d_in[4];
    const int*   seq_length  = (const int*)d_in[5];
    float*       scores      = (float*)d_out;

    cudaFuncSetAttribute(fused_kernel,
                         cudaFuncAttributeMaxDynamicSharedMemorySize,
                         GEMM_SMEM_BYTES);

    fused_kernel<<<NCTAS, 256, GEMM_SMEM_BYTES>>>(
        item_table, user_table, memory_init, user_id, seq, seq_length, scores);
}